// round 9
// baseline (speedup 1.0000x reference)
#include <cuda_runtime.h>
#include <math.h>
#include <stdint.h>

#define B_   2
#define T_   2048
#define C_   768
#define H_   12
#define DH_  64
#define LOG2E 1.4426950408889634f
#define SK   20   // smem k-stride (16 data + 4 pad) -> conflict-free frag LDS

// Scratch (device globals — no allocation allowed)
__device__ float g_q[B_ * T_ * C_];
__device__ float g_k[B_ * T_ * C_];
__device__ float g_v[B_ * T_ * C_];
__device__ float g_att[B_ * T_ * C_];
__device__ float g_partial[B_ * H_ * T_ * 16];      // per (row, colTile) partial sum(exp)
__device__ float g_invsum[B_ * H_ * T_];            // per row: 1/sum(exp)
__device__ float g_pvpart[B_ * H_ * 16 * 4 * 128 * DH_];  // pv k-split partials

// ---------------------------------------------------------------------------
__device__ __forceinline__ uint32_t f2tf(float v) {
    uint32_t r;
    asm("cvt.rna.tf32.f32 %0, %1;" : "=r"(r) : "f"(v));
    return r;
}

__device__ __forceinline__ void mma8(float4& d, const uint32_t* a, const uint32_t* b) {
    asm("mma.sync.aligned.m16n8k8.row.col.f32.tf32.tf32.f32 "
        "{%0,%1,%2,%3}, {%4,%5,%6,%7}, {%8,%9}, {%0,%1,%2,%3};"
        : "+f"(d.x), "+f"(d.y), "+f"(d.z), "+f"(d.w)
        : "r"(a[0]), "r"(a[1]), "r"(a[2]), "r"(a[3]), "r"(b[0]), "r"(b[1]));
}

__device__ __forceinline__ void cvtstore(uint32_t (*Sh)[SK], uint32_t (*Sl)[SK],
                                         int row, int ko, float4 v) {
    uint32_t h;
    h = f2tf(v.x); Sh[row][ko + 0] = h; Sl[row][ko + 0] = f2tf(v.x - __uint_as_float(h));
    h = f2tf(v.y); Sh[row][ko + 1] = h; Sl[row][ko + 1] = f2tf(v.y - __uint_as_float(h));
    h = f2tf(v.z); Sh[row][ko + 2] = h; Sl[row][ko + 2] = f2tf(v.z - __uint_as_float(h));
    h = f2tf(v.w); Sh[row][ko + 3] = h; Sl[row][ko + 3] = f2tf(v.w - __uint_as_float(h));
}

// ---------------------------------------------------------------------------
// Shared NT-GEMM body (3xTF32), 128x128 tile, register-staged double buffer.
// ---------------------------------------------------------------------------
__device__ __forceinline__ void gemm_body(const float* __restrict__ A,
                                          const float* __restrict__ Bm,
                                          float* __restrict__ C,
                                          int K, int lda, int ldb, int ldc,
                                          int m0, int n0) {
    __shared__ uint32_t Ah[128][SK], Al[128][SK], Bh[128][SK], Bl[128][SK];
    const int tid = threadIdx.x;
    const int warp = tid >> 5, lane = tid & 31;
    const int wm = (warp >> 2) * 64, wn = (warp & 3) * 32;
    const int r = lane >> 2, c = lane & 3;
    const int row0 = tid >> 2, ko0 = (tid & 3) << 2;           // it=0 coords
    const int row1 = (tid + 256) >> 2, ko1 = ko0;              // it=1 coords

    float4 acc[4][4];
#pragma unroll
    for (int i = 0; i < 4; i++)
#pragma unroll
        for (int j = 0; j < 4; j++) acc[i][j] = make_float4(0, 0, 0, 0);

    float4 sa0 = *(const float4*)(A + (size_t)(m0 + row0) * lda + ko0);
    float4 sa1 = *(const float4*)(A + (size_t)(m0 + row1) * lda + ko1);
    float4 sb0 = *(const float4*)(Bm + (size_t)(n0 + row0) * ldb + ko0);
    float4 sb1 = *(const float4*)(Bm + (size_t)(n0 + row1) * ldb + ko1);

    for (int k0 = 0; k0 < K; k0 += 16) {
        cvtstore(Ah, Al, row0, ko0, sa0);
        cvtstore(Ah, Al, row1, ko1, sa1);
        cvtstore(Bh, Bl, row0, ko0, sb0);
        cvtstore(Bh, Bl, row1, ko1, sb1);
        __syncthreads();
        if (k0 + 16 < K) {
            sa0 = *(const float4*)(A + (size_t)(m0 + row0) * lda + k0 + 16 + ko0);
            sa1 = *(const float4*)(A + (size_t)(m0 + row1) * lda + k0 + 16 + ko1);
            sb0 = *(const float4*)(Bm + (size_t)(n0 + row0) * ldb + k0 + 16 + ko0);
            sb1 = *(const float4*)(Bm + (size_t)(n0 + row1) * ldb + k0 + 16 + ko1);
        }
#pragma unroll
        for (int kb = 0; kb < 16; kb += 8) {
            uint32_t bhf[4][2], blf[4][2];
#pragma unroll
            for (int nj = 0; nj < 4; nj++) {
                int col = wn + nj * 8 + r;
                bhf[nj][0] = Bh[col][kb + c]; bhf[nj][1] = Bh[col][kb + c + 4];
                blf[nj][0] = Bl[col][kb + c]; blf[nj][1] = Bl[col][kb + c + 4];
            }
#pragma unroll
            for (int mi = 0; mi < 4; mi++) {
                int rw = wm + mi * 16 + r;
                uint32_t ah[4], al[4];
                ah[0] = Ah[rw][kb + c];     ah[1] = Ah[rw + 8][kb + c];
                ah[2] = Ah[rw][kb + c + 4]; ah[3] = Ah[rw + 8][kb + c + 4];
                al[0] = Al[rw][kb + c];     al[1] = Al[rw + 8][kb + c];
                al[2] = Al[rw][kb + c + 4]; al[3] = Al[rw + 8][kb + c + 4];
#pragma unroll
                for (int nj = 0; nj < 4; nj++) {
                    mma8(acc[mi][nj], al, bhf[nj]);
                    mma8(acc[mi][nj], ah, blf[nj]);
                    mma8(acc[mi][nj], ah, bhf[nj]);
                }
            }
        }
        __syncthreads();
    }
#pragma unroll
    for (int mi = 0; mi < 4; mi++)
#pragma unroll
        for (int nj = 0; nj < 4; nj++) {
            int gm = m0 + wm + mi * 16 + r;
            int gn = n0 + wn + nj * 8 + 2 * c;
            *(float2*)&C[(size_t)gm * ldc + gn]       = make_float2(acc[mi][nj].x, acc[mi][nj].y);
            *(float2*)&C[(size_t)(gm + 8) * ldc + gn] = make_float2(acc[mi][nj].z, acc[mi][nj].w);
        }
}

// Fused QKV projection: grid (18, 32)
__global__ void __launch_bounds__(256) gemm_qkv(const float* __restrict__ x,
                                                const float* __restrict__ wq,
                                                const float* __restrict__ wk,
                                                const float* __restrict__ wv,
                                                float* __restrict__ q,
                                                float* __restrict__ k,
                                                float* __restrict__ v) {
    const int nb = blockIdx.x;
    const int sel = nb / 6;
    const int n0 = (nb % 6) * 128;
    const int m0 = blockIdx.y * 128;
    const float* W = (sel == 0) ? wq : (sel == 1) ? wk : wv;
    float* O = (sel == 0) ? q : (sel == 1) ? k : v;
    gemm_body(x, W, O, C_, C_, C_, C_, m0, n0);
}

// Final projection: grid (6, 32)
__global__ void __launch_bounds__(256) gemm_final(const float* __restrict__ A,
                                                  const float* __restrict__ Wo,
                                                  float* __restrict__ C) {
    gemm_body(A, Wo, C, C_, C_, C_, C_, blockIdx.y * 128, blockIdx.x * 128);
}

// ---------------------------------------------------------------------------
// Scores -> store UNNORMALIZED exp(0.125*QK) (masked->0) + row partial sums.
// grid (16, 16, 24). Register-staged double buffer.
// ---------------------------------------------------------------------------
__global__ void __launch_bounds__(256) scores_tc(const float* __restrict__ Q,
                                                 const float* __restrict__ Kt,
                                                 float* __restrict__ W,
                                                 float* __restrict__ partial) {
    const int z = blockIdx.z;
    const int b = z / H_, h = z % H_;
    const int m0 = blockIdx.y * 128, n0 = blockIdx.x * 128;
    const int tid = threadIdx.x;
    float* Cz = W + (size_t)z * T_ * T_;

    if (n0 > m0) {  // fully masked tile -> zeros; no partials
        const float4 zz = make_float4(0, 0, 0, 0);
        for (int idx = tid; idx < 128 * 32; idx += 256) {
            int row = idx >> 5, c4 = (idx & 31) << 2;
            *(float4*)&Cz[(size_t)(m0 + row) * T_ + n0 + c4] = zz;
        }
        return;
    }

    __shared__ uint32_t Ah[128][SK], Al[128][SK], Bh[128][SK], Bl[128][SK];
    __shared__ float spart[128][4];
    const int warp = tid >> 5, lane = tid & 31;
    const int wm = (warp >> 2) * 64, wn = (warp & 3) * 32;
    const int r = lane >> 2, c = lane & 3;
    const float* Ap = Q + (size_t)b * T_ * C_ + h * DH_;
    const float* Bp = Kt + (size_t)b * T_ * C_ + h * DH_;
    const int row0 = tid >> 2, ko0 = (tid & 3) << 2;
    const int row1 = (tid + 256) >> 2, ko1 = ko0;

    float4 acc[4][4];
#pragma unroll
    for (int i = 0; i < 4; i++)
#pragma unroll
        for (int j = 0; j < 4; j++) acc[i][j] = make_float4(0, 0, 0, 0);

    float4 sa0 = *(const float4*)(Ap + (size_t)(m0 + row0) * C_ + ko0);
    float4 sa1 = *(const float4*)(Ap + (size_t)(m0 + row1) * C_ + ko1);
    float4 sb0 = *(const float4*)(Bp + (size_t)(n0 + row0) * C_ + ko0);
    float4 sb1 = *(const float4*)(Bp + (size_t)(n0 + row1) * C_ + ko1);

#pragma unroll
    for (int k0 = 0; k0 < DH_; k0 += 16) {
        cvtstore(Ah, Al, row0, ko0, sa0);
        cvtstore(Ah, Al, row1, ko1, sa1);
        cvtstore(Bh, Bl, row0, ko0, sb0);
        cvtstore(Bh, Bl, row1, ko1, sb1);
        __syncthreads();
        if (k0 + 16 < DH_) {
            sa0 = *(const float4*)(Ap + (size_t)(m0 + row0) * C_ + k0 + 16 + ko0);
            sa1 = *(const float4*)(Ap + (size_t)(m0 + row1) * C_ + k0 + 16 + ko1);
            sb0 = *(const float4*)(Bp + (size_t)(n0 + row0) * C_ + k0 + 16 + ko0);
            sb1 = *(const float4*)(Bp + (size_t)(n0 + row1) * C_ + k0 + 16 + ko1);
        }
#pragma unroll
        for (int kb = 0; kb < 16; kb += 8) {
            uint32_t bhf[4][2], blf[4][2];
#pragma unroll
            for (int nj = 0; nj < 4; nj++) {
                int col = wn + nj * 8 + r;
                bhf[nj][0] = Bh[col][kb + c]; bhf[nj][1] = Bh[col][kb + c + 4];
                blf[nj][0] = Bl[col][kb + c]; blf[nj][1] = Bl[col][kb + c + 4];
            }
#pragma unroll
            for (int mi = 0; mi < 4; mi++) {
                int rw = wm + mi * 16 + r;
                uint32_t ah[4], al[4];
                ah[0] = Ah[rw][kb + c];     ah[1] = Ah[rw + 8][kb + c];
                ah[2] = Ah[rw][kb + c + 4]; ah[3] = Ah[rw + 8][kb + c + 4];
                al[0] = Al[rw][kb + c];     al[1] = Al[rw + 8][kb + c];
                al[2] = Al[rw][kb + c + 4]; al[3] = Al[rw + 8][kb + c + 4];
#pragma unroll
                for (int nj = 0; nj < 4; nj++) {
                    mma8(acc[mi][nj], al, bhf[nj]);
                    mma8(acc[mi][nj], ah, blf[nj]);
                    mma8(acc[mi][nj], ah, bhf[nj]);
                }
            }
        }
        __syncthreads();
    }

    const bool diag = (n0 == m0);
#pragma unroll
    for (int mi = 0; mi < 4; mi++) {
        float se0 = 0.0f, se1 = 0.0f;
        int gm = m0 + wm + mi * 16 + r;
#pragma unroll
        for (int nj = 0; nj < 4; nj++) {
            int gn = n0 + wn + nj * 8 + 2 * c;
            float e0 = exp2f(0.125f * LOG2E * acc[mi][nj].x);
            float e1 = exp2f(0.125f * LOG2E * acc[mi][nj].y);
            float e2 = exp2f(0.125f * LOG2E * acc[mi][nj].z);
            float e3 = exp2f(0.125f * LOG2E * acc[mi][nj].w);
            if (diag) {
                if (gn > gm) e0 = 0.0f;
                if (gn + 1 > gm) e1 = 0.0f;
                if (gn > gm + 8) e2 = 0.0f;
                if (gn + 1 > gm + 8) e3 = 0.0f;
            }
            se0 += e0 + e1;
            se1 += e2 + e3;
            *(float2*)&Cz[(size_t)gm * T_ + gn]       = make_float2(e0, e1);
            *(float2*)&Cz[(size_t)(gm + 8) * T_ + gn] = make_float2(e2, e3);
        }
        se0 += __shfl_xor_sync(0xffffffffu, se0, 1);
        se0 += __shfl_xor_sync(0xffffffffu, se0, 2);
        se1 += __shfl_xor_sync(0xffffffffu, se1, 1);
        se1 += __shfl_xor_sync(0xffffffffu, se1, 2);
        if (c == 0) {
            spart[wm + mi * 16 + r][warp & 3]     = se0;
            spart[wm + mi * 16 + r + 8][warp & 3] = se1;
        }
    }
    __syncthreads();
    if (tid < 128) {
        float s = spart[tid][0] + spart[tid][1] + spart[tid][2] + spart[tid][3];
        partial[((size_t)z * T_ + m0 + tid) * 16 + (n0 >> 7)] = s;
    }
}

// ---------------------------------------------------------------------------
// Reduce partials -> 1/rowsum.
// ---------------------------------------------------------------------------
__global__ void __launch_bounds__(256) reduce_kernel(const float* __restrict__ partial,
                                                     float* __restrict__ invsum) {
    const int rg = blockIdx.x * 256 + threadIdx.x;
    const int i = rg % T_;
    const int ntmax = i >> 7;
    float s = 0.0f;
    const float* p = partial + (size_t)rg * 16;
    for (int nt = 0; nt <= ntmax; nt++) s += p[nt];
    invsum[rg] = 1.0f / s;
}

// ---------------------------------------------------------------------------
// PV k-split, fused with normalization + weights writeback:
//   reads unnormalized e, w = e * invsum[row], writes w back (weights output),
//   accumulates partial O = w @ V.
// grid (4, 16, 24); mt reversed (heavy first).
// ---------------------------------------------------------------------------
__global__ void __launch_bounds__(256) pv_split_tc(float* __restrict__ W,
                                                   const float* __restrict__ V,
                                                   float* __restrict__ part,
                                                   const float* __restrict__ invsum) {
    const int ck = blockIdx.x;
    const int mt = 15 - blockIdx.y;
    const int z = blockIdx.z;
    const int m0 = mt * 128;
    const int kbeg = ck * 512;
    const int kend = min(kbeg + 512, m0 + 128);
    if (kbeg >= kend) return;

    const int b = z / H_, h = z % H_;
    const int tid = threadIdx.x;
    const int warp = tid >> 5, lane = tid & 31;
    const int wm = (warp >> 2) * 64, wn = (warp & 3) * 16;
    const int r = lane >> 2, c = lane & 3;

    float* Wz = W + (size_t)z * T_ * T_;
    const float* Vp = V + (size_t)b * T_ * C_ + h * DH_;

    __shared__ uint32_t Ah[128][SK], Al[128][SK], Bh[64][SK], Bl[64][SK];
    __shared__ float il_s[128];

    if (tid < 128) il_s[tid] = invsum[(size_t)z * T_ + m0 + tid];

    const int row0 = tid >> 2, ko0 = (tid & 3) << 2;
    const int row1 = (tid + 256) >> 2, ko1 = ko0;
    const int kr = tid >> 4, nc = (tid & 15) << 2;

    float4 acc[4][2];
#pragma unroll
    for (int i = 0; i < 4; i++)
#pragma unroll
        for (int j = 0; j < 2; j++) acc[i][j] = make_float4(0, 0, 0, 0);

    float4 sa0 = *(const float4*)(Wz + (size_t)(m0 + row0) * T_ + kbeg + ko0);
    float4 sa1 = *(const float4*)(Wz + (size_t)(m0 + row1) * T_ + kbeg + ko1);
    float4 sb  = *(const float4*)(Vp + (size_t)(kbeg + kr) * C_ + nc);
    __syncthreads();   // il_s visible before first store

    for (int k0 = kbeg; k0 < kend; k0 += 16) {
        {   // normalize, write back weights, stage to smem
            float il0 = il_s[row0], il1 = il_s[row1];
            sa0.x *= il0; sa0.y *= il0; sa0.z *= il0; sa0.w *= il0;
            sa1.x *= il1; sa1.y *= il1; sa1.z *= il1; sa1.w *= il1;
            *(float4*)(Wz + (size_t)(m0 + row0) * T_ + k0 + ko0) = sa0;
            *(float4*)(Wz + (size_t)(m0 + row1) * T_ + k0 + ko1) = sa1;
            cvtstore(Ah, Al, row0, ko0, sa0);
            cvtstore(Ah, Al, row1, ko1, sa1);
            uint32_t hh;
            hh = f2tf(sb.x); Bh[nc + 0][kr] = hh; Bl[nc + 0][kr] = f2tf(sb.x - __uint_as_float(hh));
            hh = f2tf(sb.y); Bh[nc + 1][kr] = hh; Bl[nc + 1][kr] = f2tf(sb.y - __uint_as_float(hh));
            hh = f2tf(sb.z); Bh[nc + 2][kr] = hh; Bl[nc + 2][kr] = f2tf(sb.z - __uint_as_float(hh));
            hh = f2tf(sb.w); Bh[nc + 3][kr] = hh; Bl[nc + 3][kr] = f2tf(sb.w - __uint_as_float(hh));
        }
        __syncthreads();
        if (k0 + 16 < kend) {
            sa0 = *(const float4*)(Wz + (size_t)(m0 + row0) * T_ + k0 + 16 + ko0);
            sa1 = *(const float4*)(Wz + (size_t)(m0 + row1) * T_ + k0 + 16 + ko1);
            sb  = *(const float4*)(Vp + (size_t)(k0 + 16 + kr) * C_ + nc);
        }
#pragma unroll
        for (int kb = 0; kb < 16; kb += 8) {
            uint32_t bhf[2][2], blf[2][2];
#pragma unroll
            for (int nj = 0; nj < 2; nj++) {
                int col = wn + nj * 8 + r;
                bhf[nj][0] = Bh[col][kb + c]; bhf[nj][1] = Bh[col][kb + c + 4];
                blf[nj][0] = Bl[col][kb + c]; blf[nj][1] = Bl[col][kb + c + 4];
            }
#pragma unroll
            for (int mi = 0; mi < 4; mi++) {
                int rw = wm + mi * 16 + r;
                uint32_t ah[4], al[4];
                ah[0] = Ah[rw][kb + c];     ah[1] = Ah[rw + 8][kb + c];
                ah[2] = Ah[rw][kb + c + 4]; ah[3] = Ah[rw + 8][kb + c + 4];
                al[0] = Al[rw][kb + c];     al[1] = Al[rw + 8][kb + c];
                al[2] = Al[rw][kb + c + 4]; al[3] = Al[rw + 8][kb + c + 4];
#pragma unroll
                for (int nj = 0; nj < 2; nj++) {
                    mma8(acc[mi][nj], al, bhf[nj]);
                    mma8(acc[mi][nj], ah, blf[nj]);
                    mma8(acc[mi][nj], ah, bhf[nj]);
                }
            }
        }
        __syncthreads();
    }

    float* P = part + ((size_t)(z * 16 + mt) * 4 + ck) * (128 * DH_);
#pragma unroll
    for (int mi = 0; mi < 4; mi++)
#pragma unroll
        for (int nj = 0; nj < 2; nj++) {
            int lr = wm + mi * 16 + r;
            int gn = wn + nj * 8 + 2 * c;
            *(float2*)&P[(size_t)lr * DH_ + gn]       = make_float2(acc[mi][nj].x, acc[mi][nj].y);
            *(float2*)&P[(size_t)(lr + 8) * DH_ + gn] = make_float2(acc[mi][nj].z, acc[mi][nj].w);
        }
}

// ---------------------------------------------------------------------------
// Sum pv partials -> O (g_att layout [B,T,C]). grid (384), 256 thr.
// ---------------------------------------------------------------------------
__global__ void __launch_bounds__(256) pv_reduce(const float* __restrict__ part,
                                                 float* __restrict__ O) {
    const int blk = blockIdx.x;            // z*16 + mt
    const int z = blk >> 4, mt = blk & 15;
    const int b = z / H_, h = z % H_;
    const int m0 = mt * 128;
    const int nch = (mt >> 2) + 1;         // ceil((mt+1)*128/512)
    const float* p = part + (size_t)blk * 4 * (128 * DH_);

    for (int idx = threadIdx.x * 4; idx < 128 * DH_; idx += 256 * 4) {
        float4 s = *(const float4*)(p + idx);
        for (int c2 = 1; c2 < nch; c2++) {
            float4 t = *(const float4*)(p + (size_t)c2 * 128 * DH_ + idx);
            s.x += t.x; s.y += t.y; s.z += t.z; s.w += t.w;
        }
        const int row = idx >> 6, n = idx & 63;
        *(float4*)&O[(size_t)(b * T_ + m0 + row) * C_ + h * DH_ + n] = s;
    }
}

// ---------------------------------------------------------------------------
extern "C" void kernel_launch(void* const* d_in, const int* in_sizes, int n_in,
                              void* d_out, int out_size) {
    const float* x   = (const float*)d_in[0];
    const float* w_q = (const float*)d_in[1];
    const float* w_k = (const float*)d_in[2];
    const float* w_v = (const float*)d_in[3];
    const float* w_o = (const float*)d_in[4];

    float* qp; cudaGetSymbolAddress((void**)&qp, g_q);
    float* kp; cudaGetSymbolAddress((void**)&kp, g_k);
    float* vp; cudaGetSymbolAddress((void**)&vp, g_v);
    float* ap; cudaGetSymbolAddress((void**)&ap, g_att);
    float* pp; cudaGetSymbolAddress((void**)&pp, g_partial);
    float* ip; cudaGetSymbolAddress((void**)&ip, g_invsum);
    float* vv; cudaGetSymbolAddress((void**)&vv, g_pvpart);

    float* final_out = (float*)d_out;                       // [B,T,C]
    float* w_out = (float*)d_out + (size_t)B_ * T_ * C_;    // [B,H,T,T]

    const dim3 blk(256);

    gemm_qkv<<<dim3(18, 32), blk>>>(x, w_q, w_k, w_v, qp, kp, vp);

    scores_tc<<<dim3(T_ / 128, T_ / 128, B_ * H_), blk>>>(qp, kp, w_out, pp);

    reduce_kernel<<<(B_ * H_ * T_) / 256, blk>>>(pp, ip);

    pv_split_tc<<<dim3(4, 16, 24), blk>>>(w_out, vp, vv, ip);

    pv_reduce<<<B_ * H_ * 16, blk>>>(vv, ap);

    gemm_final<<<dim3(6, 32), blk>>>(ap, w_o, final_out);
}

// round 10
// speedup vs baseline: 1.1293x; 1.1293x over previous
#include <cuda_runtime.h>
#include <math.h>
#include <stdint.h>

#define B_   2
#define T_   2048
#define C_   768
#define H_   12
#define DH_  64
#define LOG2E 1.4426950408889634f
#define SKA  20   // row stride (16 data + 4 pad); uint2 or u32 flavors

// Scratch (device globals — no allocation allowed)
__device__ float g_q[B_ * T_ * C_];
__device__ float g_k[B_ * T_ * C_];
__device__ float g_v[B_ * T_ * C_];
__device__ float g_att[B_ * T_ * C_];
__device__ float g_partial[B_ * H_ * T_ * 16];      // per (row, colTile) partial sum(exp)
__device__ float g_invsum[B_ * H_ * T_];            // per row: 1/sum(exp)
__device__ float g_pvpart[B_ * H_ * 16 * 4 * 128 * DH_];  // pv k-split partials

// ---------------------------------------------------------------------------
__device__ __forceinline__ uint32_t f2tf(float v) {
    uint32_t r;
    asm("cvt.rna.tf32.f32 %0, %1;" : "=r"(r) : "f"(v));
    return r;
}

__device__ __forceinline__ void mma8(float4& d, const uint32_t* a, const uint32_t* b) {
    asm("mma.sync.aligned.m16n8k8.row.col.f32.tf32.tf32.f32 "
        "{%0,%1,%2,%3}, {%4,%5,%6,%7}, {%8,%9}, {%0,%1,%2,%3};"
        : "+f"(d.x), "+f"(d.y), "+f"(d.z), "+f"(d.w)
        : "r"(a[0]), "r"(a[1]), "r"(a[2]), "r"(a[3]), "r"(b[0]), "r"(b[1]));
}

// hi/lo interleaved store (one uint2 per element)
__device__ __forceinline__ void cvt2(uint2 (*S)[SKA], int row, int ko, float4 v) {
    uint32_t h;
    h = f2tf(v.x); S[row][ko + 0] = make_uint2(h, f2tf(v.x - __uint_as_float(h)));
    h = f2tf(v.y); S[row][ko + 1] = make_uint2(h, f2tf(v.y - __uint_as_float(h)));
    h = f2tf(v.z); S[row][ko + 2] = make_uint2(h, f2tf(v.z - __uint_as_float(h)));
    h = f2tf(v.w); S[row][ko + 3] = make_uint2(h, f2tf(v.w - __uint_as_float(h)));
}
// hi-only store
__device__ __forceinline__ void cvt1(uint32_t (*S)[SKA], int row, int ko, float4 v) {
    S[row][ko + 0] = f2tf(v.x);
    S[row][ko + 1] = f2tf(v.y);
    S[row][ko + 2] = f2tf(v.z);
    S[row][ko + 3] = f2tf(v.w);
}

// ---------------------------------------------------------------------------
// 3-term NT GEMM body (A,B both hi/lo interleaved), 128x128 tile.
// ---------------------------------------------------------------------------
__device__ __forceinline__ void gemm3_body(const float* __restrict__ A,
                                           const float* __restrict__ Bm,
                                           float* __restrict__ C,
                                           int K, int lda, int ldb, int ldc,
                                           int m0, int n0) {
    __shared__ uint2 As[128][SKA], Bs[128][SKA];
    const int tid = threadIdx.x;
    const int warp = tid >> 5, lane = tid & 31;
    const int wm = (warp >> 2) * 64, wn = (warp & 3) * 32;
    const int r = lane >> 2, c = lane & 3;
    const int row0 = tid >> 2, ko0 = (tid & 3) << 2;
    const int row1 = (tid + 256) >> 2;

    float4 acc[4][4];
#pragma unroll
    for (int i = 0; i < 4; i++)
#pragma unroll
        for (int j = 0; j < 4; j++) acc[i][j] = make_float4(0, 0, 0, 0);

    for (int k0 = 0; k0 < K; k0 += 16) {
        __syncthreads();
        cvt2(As, row0, ko0, *(const float4*)(A + (size_t)(m0 + row0) * lda + k0 + ko0));
        cvt2(As, row1, ko0, *(const float4*)(A + (size_t)(m0 + row1) * lda + k0 + ko0));
        cvt2(Bs, row0, ko0, *(const float4*)(Bm + (size_t)(n0 + row0) * ldb + k0 + ko0));
        cvt2(Bs, row1, ko0, *(const float4*)(Bm + (size_t)(n0 + row1) * ldb + k0 + ko0));
        __syncthreads();
#pragma unroll
        for (int kb = 0; kb < 16; kb += 8) {
            uint32_t bh[4][2], bl[4][2];
#pragma unroll
            for (int nj = 0; nj < 4; nj++) {
                int col = wn + nj * 8 + r;
                uint2 b0 = Bs[col][kb + c], b1 = Bs[col][kb + c + 4];
                bh[nj][0] = b0.x; bh[nj][1] = b1.x;
                bl[nj][0] = b0.y; bl[nj][1] = b1.y;
            }
#pragma unroll
            for (int mi = 0; mi < 4; mi++) {
                int rw = wm + mi * 16 + r;
                uint2 a0 = As[rw][kb + c],     a1 = As[rw + 8][kb + c];
                uint2 a2 = As[rw][kb + c + 4], a3 = As[rw + 8][kb + c + 4];
                uint32_t ah[4] = {a0.x, a1.x, a2.x, a3.x};
                uint32_t al[4] = {a0.y, a1.y, a2.y, a3.y};
#pragma unroll
                for (int nj = 0; nj < 4; nj++) {
                    mma8(acc[mi][nj], al, bh[nj]);
                    mma8(acc[mi][nj], ah, bl[nj]);
                    mma8(acc[mi][nj], ah, bh[nj]);
                }
            }
        }
    }
#pragma unroll
    for (int mi = 0; mi < 4; mi++)
#pragma unroll
        for (int nj = 0; nj < 4; nj++) {
            int gm = m0 + wm + mi * 16 + r;
            int gn = n0 + wn + nj * 8 + 2 * c;
            *(float2*)&C[(size_t)gm * ldc + gn]       = make_float2(acc[mi][nj].x, acc[mi][nj].y);
            *(float2*)&C[(size_t)(gm + 8) * ldc + gn] = make_float2(acc[mi][nj].z, acc[mi][nj].w);
        }
}

// Fused QKV projection: grid (18, 32)
__global__ void __launch_bounds__(256) gemm_qkv(const float* __restrict__ x,
                                                const float* __restrict__ wq,
                                                const float* __restrict__ wk,
                                                const float* __restrict__ wv,
                                                float* __restrict__ q,
                                                float* __restrict__ k,
                                                float* __restrict__ v) {
    const int nb = blockIdx.x;
    const int sel = nb / 6;
    const int n0 = (nb % 6) * 128;
    const int m0 = blockIdx.y * 128;
    const float* W = (sel == 0) ? wq : (sel == 1) ? wk : wv;
    float* O = (sel == 0) ? q : (sel == 1) ? k : v;
    gemm3_body(x, W, O, C_, C_, C_, C_, m0, n0);
}

// ---------------------------------------------------------------------------
// Final projection, 2-term (A hi/lo, B hi only): grid (6, 32)
// ---------------------------------------------------------------------------
__global__ void __launch_bounds__(256) gemm_final(const float* __restrict__ A,
                                                  const float* __restrict__ Wo,
                                                  float* __restrict__ C) {
    __shared__ uint2 As[128][SKA];
    __shared__ uint32_t Bs[128][SKA];
    const int m0 = blockIdx.y * 128, n0 = blockIdx.x * 128;
    const int tid = threadIdx.x;
    const int warp = tid >> 5, lane = tid & 31;
    const int wm = (warp >> 2) * 64, wn = (warp & 3) * 32;
    const int r = lane >> 2, c = lane & 3;
    const int row0 = tid >> 2, ko0 = (tid & 3) << 2;
    const int row1 = (tid + 256) >> 2;

    float4 acc[4][4];
#pragma unroll
    for (int i = 0; i < 4; i++)
#pragma unroll
        for (int j = 0; j < 4; j++) acc[i][j] = make_float4(0, 0, 0, 0);

    for (int k0 = 0; k0 < C_; k0 += 16) {
        __syncthreads();
        cvt2(As, row0, ko0, *(const float4*)(A + (size_t)(m0 + row0) * C_ + k0 + ko0));
        cvt2(As, row1, ko0, *(const float4*)(A + (size_t)(m0 + row1) * C_ + k0 + ko0));
        cvt1(Bs, row0, ko0, *(const float4*)(Wo + (size_t)(n0 + row0) * C_ + k0 + ko0));
        cvt1(Bs, row1, ko0, *(const float4*)(Wo + (size_t)(n0 + row1) * C_ + k0 + ko0));
        __syncthreads();
#pragma unroll
        for (int kb = 0; kb < 16; kb += 8) {
            uint32_t bh[4][2];
#pragma unroll
            for (int nj = 0; nj < 4; nj++) {
                int col = wn + nj * 8 + r;
                bh[nj][0] = Bs[col][kb + c]; bh[nj][1] = Bs[col][kb + c + 4];
            }
#pragma unroll
            for (int mi = 0; mi < 4; mi++) {
                int rw = wm + mi * 16 + r;
                uint2 a0 = As[rw][kb + c],     a1 = As[rw + 8][kb + c];
                uint2 a2 = As[rw][kb + c + 4], a3 = As[rw + 8][kb + c + 4];
                uint32_t ah[4] = {a0.x, a1.x, a2.x, a3.x};
                uint32_t al[4] = {a0.y, a1.y, a2.y, a3.y};
#pragma unroll
                for (int nj = 0; nj < 4; nj++) {
                    mma8(acc[mi][nj], al, bh[nj]);
                    mma8(acc[mi][nj], ah, bh[nj]);
                }
            }
        }
    }
#pragma unroll
    for (int mi = 0; mi < 4; mi++)
#pragma unroll
        for (int nj = 0; nj < 4; nj++) {
            int gm = m0 + wm + mi * 16 + r;
            int gn = n0 + wn + nj * 8 + 2 * c;
            *(float2*)&C[(size_t)gm * C_ + gn]       = make_float2(acc[mi][nj].x, acc[mi][nj].y);
            *(float2*)&C[(size_t)(gm + 8) * C_ + gn] = make_float2(acc[mi][nj].z, acc[mi][nj].w);
        }
}

// ---------------------------------------------------------------------------
// Scores -> store UNNORMALIZED exp(0.125*QK) (masked->0) + row partial sums.
// 3-term. grid (16, 16, 24)
// ---------------------------------------------------------------------------
__global__ void __launch_bounds__(256) scores_tc(const float* __restrict__ Q,
                                                 const float* __restrict__ Kt,
                                                 float* __restrict__ W,
                                                 float* __restrict__ partial) {
    const int z = blockIdx.z;
    const int b = z / H_, h = z % H_;
    const int m0 = blockIdx.y * 128, n0 = blockIdx.x * 128;
    const int tid = threadIdx.x;
    float* Cz = W + (size_t)z * T_ * T_;

    if (n0 > m0) {  // fully masked tile -> zeros; no partials
        const float4 zz = make_float4(0, 0, 0, 0);
        for (int idx = tid; idx < 128 * 32; idx += 256) {
            int row = idx >> 5, c4 = (idx & 31) << 2;
            *(float4*)&Cz[(size_t)(m0 + row) * T_ + n0 + c4] = zz;
        }
        return;
    }

    __shared__ uint2 As[128][SKA], Bs[128][SKA];
    __shared__ float spart[128][4];
    const int warp = tid >> 5, lane = tid & 31;
    const int wm = (warp >> 2) * 64, wn = (warp & 3) * 32;
    const int r = lane >> 2, c = lane & 3;
    const float* Ap = Q + (size_t)b * T_ * C_ + h * DH_;
    const float* Bp = Kt + (size_t)b * T_ * C_ + h * DH_;
    const int row0 = tid >> 2, ko0 = (tid & 3) << 2;
    const int row1 = (tid + 256) >> 2;

    float4 acc[4][4];
#pragma unroll
    for (int i = 0; i < 4; i++)
#pragma unroll
        for (int j = 0; j < 4; j++) acc[i][j] = make_float4(0, 0, 0, 0);

#pragma unroll
    for (int k0 = 0; k0 < DH_; k0 += 16) {
        __syncthreads();
        cvt2(As, row0, ko0, *(const float4*)(Ap + (size_t)(m0 + row0) * C_ + k0 + ko0));
        cvt2(As, row1, ko0, *(const float4*)(Ap + (size_t)(m0 + row1) * C_ + k0 + ko0));
        cvt2(Bs, row0, ko0, *(const float4*)(Bp + (size_t)(n0 + row0) * C_ + k0 + ko0));
        cvt2(Bs, row1, ko0, *(const float4*)(Bp + (size_t)(n0 + row1) * C_ + k0 + ko0));
        __syncthreads();
#pragma unroll
        for (int kb = 0; kb < 16; kb += 8) {
            uint32_t bh[4][2], bl[4][2];
#pragma unroll
            for (int nj = 0; nj < 4; nj++) {
                int col = wn + nj * 8 + r;
                uint2 b0 = Bs[col][kb + c], b1 = Bs[col][kb + c + 4];
                bh[nj][0] = b0.x; bh[nj][1] = b1.x;
                bl[nj][0] = b0.y; bl[nj][1] = b1.y;
            }
#pragma unroll
            for (int mi = 0; mi < 4; mi++) {
                int rw = wm + mi * 16 + r;
                uint2 a0 = As[rw][kb + c],     a1 = As[rw + 8][kb + c];
                uint2 a2 = As[rw][kb + c + 4], a3 = As[rw + 8][kb + c + 4];
                uint32_t ah[4] = {a0.x, a1.x, a2.x, a3.x};
                uint32_t al[4] = {a0.y, a1.y, a2.y, a3.y};
#pragma unroll
                for (int nj = 0; nj < 4; nj++) {
                    mma8(acc[mi][nj], al, bh[nj]);
                    mma8(acc[mi][nj], ah, bl[nj]);
                    mma8(acc[mi][nj], ah, bh[nj]);
                }
            }
        }
    }

    const bool diag = (n0 == m0);
#pragma unroll
    for (int mi = 0; mi < 4; mi++) {
        float se0 = 0.0f, se1 = 0.0f;
        int gm = m0 + wm + mi * 16 + r;
#pragma unroll
        for (int nj = 0; nj < 4; nj++) {
            int gn = n0 + wn + nj * 8 + 2 * c;
            float e0 = exp2f(0.125f * LOG2E * acc[mi][nj].x);
            float e1 = exp2f(0.125f * LOG2E * acc[mi][nj].y);
            float e2 = exp2f(0.125f * LOG2E * acc[mi][nj].z);
            float e3 = exp2f(0.125f * LOG2E * acc[mi][nj].w);
            if (diag) {
                if (gn > gm) e0 = 0.0f;
                if (gn + 1 > gm) e1 = 0.0f;
                if (gn > gm + 8) e2 = 0.0f;
                if (gn + 1 > gm + 8) e3 = 0.0f;
            }
            se0 += e0 + e1;
            se1 += e2 + e3;
            *(float2*)&Cz[(size_t)gm * T_ + gn]       = make_float2(e0, e1);
            *(float2*)&Cz[(size_t)(gm + 8) * T_ + gn] = make_float2(e2, e3);
        }
        se0 += __shfl_xor_sync(0xffffffffu, se0, 1);
        se0 += __shfl_xor_sync(0xffffffffu, se0, 2);
        se1 += __shfl_xor_sync(0xffffffffu, se1, 1);
        se1 += __shfl_xor_sync(0xffffffffu, se1, 2);
        if (c == 0) {
            spart[wm + mi * 16 + r][warp & 3]     = se0;
            spart[wm + mi * 16 + r + 8][warp & 3] = se1;
        }
    }
    __syncthreads();
    if (tid < 128) {
        float s = spart[tid][0] + spart[tid][1] + spart[tid][2] + spart[tid][3];
        partial[((size_t)z * T_ + m0 + tid) * 16 + (n0 >> 7)] = s;
    }
}

// ---------------------------------------------------------------------------
// Reduce partials -> 1/rowsum.
// ---------------------------------------------------------------------------
__global__ void __launch_bounds__(256) reduce_kernel(const float* __restrict__ partial,
                                                     float* __restrict__ invsum) {
    const int rg = blockIdx.x * 256 + threadIdx.x;
    const int i = rg % T_;
    const int ntmax = i >> 7;
    float s = 0.0f;
    const float* p = partial + (size_t)rg * 16;
    for (int nt = 0; nt <= ntmax; nt++) s += p[nt];
    invsum[rg] = 1.0f / s;
}

// ---------------------------------------------------------------------------
// Normalize weights in place over the valid prefix. One block (128thr) per row.
// ---------------------------------------------------------------------------
__global__ void __launch_bounds__(128) normalize_kernel(float* __restrict__ W,
                                                        const float* __restrict__ invsum) {
    const int rg = blockIdx.x;
    const int i = rg % T_;
    const int n4 = (i + 4) >> 2;   // ceil((i+1)/4) float4s (tail zeros scale to 0)
    const float il = invsum[rg];
    float4* row = (float4*)(W + (size_t)rg * T_);
    for (int j = threadIdx.x; j < n4; j += 128) {
        float4 v = row[j];
        v.x *= il; v.y *= il; v.z *= il; v.w *= il;
        row[j] = v;
    }
}

// ---------------------------------------------------------------------------
// PV k-split, 2-term (P hi/lo, V hi only). grid (4, 16, 24), mt reversed.
// ---------------------------------------------------------------------------
__global__ void __launch_bounds__(256) pv_split_tc(const float* __restrict__ W,
                                                   const float* __restrict__ V,
                                                   float* __restrict__ part) {
    const int ck = blockIdx.x;
    const int mt = 15 - blockIdx.y;
    const int z = blockIdx.z;
    const int m0 = mt * 128;
    const int kbeg = ck * 512;
    const int kend = min(kbeg + 512, m0 + 128);
    if (kbeg >= kend) return;

    const int b = z / H_, h = z % H_;
    const int tid = threadIdx.x;
    const int warp = tid >> 5, lane = tid & 31;
    const int wm = (warp >> 2) * 64, wn = (warp & 3) * 16;
    const int r = lane >> 2, c = lane & 3;

    const float* Wz = W + (size_t)z * T_ * T_;
    const float* Vp = V + (size_t)b * T_ * C_ + h * DH_;

    __shared__ uint2 As[128][SKA];
    __shared__ uint32_t Bs[64][SKA];

    const int row0 = tid >> 2, ko0 = (tid & 3) << 2;
    const int row1 = (tid + 256) >> 2;
    const int kr = tid >> 4, nc = (tid & 15) << 2;

    float4 acc[4][2];
#pragma unroll
    for (int i = 0; i < 4; i++)
#pragma unroll
        for (int j = 0; j < 2; j++) acc[i][j] = make_float4(0, 0, 0, 0);

    for (int k0 = kbeg; k0 < kend; k0 += 16) {
        __syncthreads();
        cvt2(As, row0, ko0, *(const float4*)(Wz + (size_t)(m0 + row0) * T_ + k0 + ko0));
        cvt2(As, row1, ko0, *(const float4*)(Wz + (size_t)(m0 + row1) * T_ + k0 + ko0));
        {
            float4 v = *(const float4*)(Vp + (size_t)(k0 + kr) * C_ + nc);
            Bs[nc + 0][kr] = f2tf(v.x);
            Bs[nc + 1][kr] = f2tf(v.y);
            Bs[nc + 2][kr] = f2tf(v.z);
            Bs[nc + 3][kr] = f2tf(v.w);
        }
        __syncthreads();
#pragma unroll
        for (int kb = 0; kb < 16; kb += 8) {
            uint32_t bh[2][2];
#pragma unroll
            for (int nj = 0; nj < 2; nj++) {
                int col = wn + nj * 8 + r;
                bh[nj][0] = Bs[col][kb + c]; bh[nj][1] = Bs[col][kb + c + 4];
            }
#pragma unroll
            for (int mi = 0; mi < 4; mi++) {
                int rw = wm + mi * 16 + r;
                uint2 a0 = As[rw][kb + c],     a1 = As[rw + 8][kb + c];
                uint2 a2 = As[rw][kb + c + 4], a3 = As[rw + 8][kb + c + 4];
                uint32_t ah[4] = {a0.x, a1.x, a2.x, a3.x};
                uint32_t al[4] = {a0.y, a1.y, a2.y, a3.y};
#pragma unroll
                for (int nj = 0; nj < 2; nj++) {
                    mma8(acc[mi][nj], al, bh[nj]);
                    mma8(acc[mi][nj], ah, bh[nj]);
                }
            }
        }
    }

    float* P = part + ((size_t)(z * 16 + mt) * 4 + ck) * (128 * DH_);
#pragma unroll
    for (int mi = 0; mi < 4; mi++)
#pragma unroll
        for (int nj = 0; nj < 2; nj++) {
            int lr = wm + mi * 16 + r;
            int gn = wn + nj * 8 + 2 * c;
            *(float2*)&P[(size_t)lr * DH_ + gn]       = make_float2(acc[mi][nj].x, acc[mi][nj].y);
            *(float2*)&P[(size_t)(lr + 8) * DH_ + gn] = make_float2(acc[mi][nj].z, acc[mi][nj].w);
        }
}

// ---------------------------------------------------------------------------
// Sum pv partials -> O (g_att layout [B,T,C]). grid (384), 256 thr.
// ---------------------------------------------------------------------------
__global__ void __launch_bounds__(256) pv_reduce(const float* __restrict__ part,
                                                 float* __restrict__ O) {
    const int blk = blockIdx.x;            // z*16 + mt
    const int z = blk >> 4, mt = blk & 15;
    const int b = z / H_, h = z % H_;
    const int m0 = mt * 128;
    const int nch = (mt >> 2) + 1;         // ceil((mt+1)*128/512)
    const float* p = part + (size_t)blk * 4 * (128 * DH_);

    for (int idx = threadIdx.x * 4; idx < 128 * DH_; idx += 256 * 4) {
        float4 s = *(const float4*)(p + idx);
        for (int c2 = 1; c2 < nch; c2++) {
            float4 t = *(const float4*)(p + (size_t)c2 * 128 * DH_ + idx);
            s.x += t.x; s.y += t.y; s.z += t.z; s.w += t.w;
        }
        const int row = idx >> 6, n = idx & 63;
        *(float4*)&O[(size_t)(b * T_ + m0 + row) * C_ + h * DH_ + n] = s;
    }
}

// ---------------------------------------------------------------------------
extern "C" void kernel_launch(void* const* d_in, const int* in_sizes, int n_in,
                              void* d_out, int out_size) {
    const float* x   = (const float*)d_in[0];
    const float* w_q = (const float*)d_in[1];
    const float* w_k = (const float*)d_in[2];
    const float* w_v = (const float*)d_in[3];
    const float* w_o = (const float*)d_in[4];

    float* qp; cudaGetSymbolAddress((void**)&qp, g_q);
    float* kp; cudaGetSymbolAddress((void**)&kp, g_k);
    float* vp; cudaGetSymbolAddress((void**)&vp, g_v);
    float* ap; cudaGetSymbolAddress((void**)&ap, g_att);
    float* pp; cudaGetSymbolAddress((void**)&pp, g_partial);
    float* ip; cudaGetSymbolAddress((void**)&ip, g_invsum);
    float* vv; cudaGetSymbolAddress((void**)&vv, g_pvpart);

    float* final_out = (float*)d_out;                       // [B,T,C]
    float* w_out = (float*)d_out + (size_t)B_ * T_ * C_;    // [B,H,T,T]

    const dim3 blk(256);

    gemm_qkv<<<dim3(18, 32), blk>>>(x, w_q, w_k, w_v, qp, kp, vp);

    scores_tc<<<dim3(T_ / 128, T_ / 128, B_ * H_), blk>>>(qp, kp, w_out, pp);

    reduce_kernel<<<(B_ * H_ * T_) / 256, blk>>>(pp, ip);

    normalize_kernel<<<B_ * H_ * T_, 128>>>(w_out, ip);

    pv_split_tc<<<dim3(4, 16, 24), blk>>>(w_out, vp, vv);

    pv_reduce<<<B_ * H_ * 16, blk>>>(vv, ap);

    gemm_final<<<dim3(6, 32), blk>>>(ap, w_o, final_out);
}

// round 11
// speedup vs baseline: 1.2012x; 1.0636x over previous
#include <cuda_runtime.h>
#include <math.h>
#include <stdint.h>

#define B_   2
#define T_   2048
#define C_   768
#define H_   12
#define DH_  64
#define LOG2E 1.4426950408889634f
#define SKA  20   // row stride (16 data + 4 pad)

// Scratch (device globals — no allocation allowed)
__device__ float g_q[B_ * T_ * C_];
__device__ float g_k[B_ * T_ * C_];
__device__ float g_v[B_ * T_ * C_];
__device__ float g_att[B_ * T_ * C_];
__device__ float g_partial[B_ * H_ * T_ * 16];      // per (row, colTile) partial sum(exp)
__device__ float g_pvpart[B_ * H_ * 16 * 4 * 128 * DH_];  // pv k-split partials

// ---------------------------------------------------------------------------
__device__ __forceinline__ uint32_t f2tf(float v) {   // rounded tf32 (B hi-only path)
    uint32_t r;
    asm("cvt.rna.tf32.f32 %0, %1;" : "=r"(r) : "f"(v));
    return r;
}

__device__ __forceinline__ void mma8(float4& d, const uint32_t* a, const uint32_t* b) {
    asm("mma.sync.aligned.m16n8k8.row.col.f32.tf32.tf32.f32 "
        "{%0,%1,%2,%3}, {%4,%5,%6,%7}, {%8,%9}, {%0,%1,%2,%3};"
        : "+f"(d.x), "+f"(d.y), "+f"(d.z), "+f"(d.w)
        : "r"(a[0]), "r"(a[1]), "r"(a[2]), "r"(a[3]), "r"(b[0]), "r"(b[1]));
}

// Truncation split: hi = raw fp32 bits (HW reads top 19), lo = v - trunc13(v).
__device__ __forceinline__ uint2 tsplit(float v) {
    uint32_t bits = __float_as_uint(v);
    float hi = __uint_as_float(bits & 0xFFFFE000u);
    return make_uint2(bits, __float_as_uint(v - hi));
}
__device__ __forceinline__ void cvt2t(uint2 (*S)[SKA], int row, int ko, float4 v) {
    S[row][ko + 0] = tsplit(v.x);
    S[row][ko + 1] = tsplit(v.y);
    S[row][ko + 2] = tsplit(v.z);
    S[row][ko + 3] = tsplit(v.w);
}
// rounded hi-only store
__device__ __forceinline__ void cvt1(uint32_t (*S)[SKA], int row, int ko, float4 v) {
    S[row][ko + 0] = f2tf(v.x);
    S[row][ko + 1] = f2tf(v.y);
    S[row][ko + 2] = f2tf(v.z);
    S[row][ko + 3] = f2tf(v.w);
}

// ---------------------------------------------------------------------------
// 3-term NT GEMM body (A,B hi/lo trunc-split), 128x128 tile.  (QKV path)
// ---------------------------------------------------------------------------
__device__ __forceinline__ void gemm3_body(const float* __restrict__ A,
                                           const float* __restrict__ Bm,
                                           float* __restrict__ C,
                                           int K, int lda, int ldb, int ldc,
                                           int m0, int n0) {
    __shared__ uint2 As[128][SKA], Bs[128][SKA];
    const int tid = threadIdx.x;
    const int warp = tid >> 5, lane = tid & 31;
    const int wm = (warp >> 2) * 64, wn = (warp & 3) * 32;
    const int r = lane >> 2, c = lane & 3;
    const int row0 = tid >> 2, ko0 = (tid & 3) << 2;
    const int row1 = (tid + 256) >> 2;

    float4 acc[4][4];
#pragma unroll
    for (int i = 0; i < 4; i++)
#pragma unroll
        for (int j = 0; j < 4; j++) acc[i][j] = make_float4(0, 0, 0, 0);

    for (int k0 = 0; k0 < K; k0 += 16) {
        __syncthreads();
        cvt2t(As, row0, ko0, *(const float4*)(A + (size_t)(m0 + row0) * lda + k0 + ko0));
        cvt2t(As, row1, ko0, *(const float4*)(A + (size_t)(m0 + row1) * lda + k0 + ko0));
        cvt2t(Bs, row0, ko0, *(const float4*)(Bm + (size_t)(n0 + row0) * ldb + k0 + ko0));
        cvt2t(Bs, row1, ko0, *(const float4*)(Bm + (size_t)(n0 + row1) * ldb + k0 + ko0));
        __syncthreads();
#pragma unroll
        for (int kb = 0; kb < 16; kb += 8) {
            uint32_t bh[4][2], bl[4][2];
#pragma unroll
            for (int nj = 0; nj < 4; nj++) {
                int col = wn + nj * 8 + r;
                uint2 b0 = Bs[col][kb + c], b1 = Bs[col][kb + c + 4];
                bh[nj][0] = b0.x; bh[nj][1] = b1.x;
                bl[nj][0] = b0.y; bl[nj][1] = b1.y;
            }
#pragma unroll
            for (int mi = 0; mi < 4; mi++) {
                int rw = wm + mi * 16 + r;
                uint2 a0 = As[rw][kb + c],     a1 = As[rw + 8][kb + c];
                uint2 a2 = As[rw][kb + c + 4], a3 = As[rw + 8][kb + c + 4];
                uint32_t ah[4] = {a0.x, a1.x, a2.x, a3.x};
                uint32_t al[4] = {a0.y, a1.y, a2.y, a3.y};
#pragma unroll
                for (int nj = 0; nj < 4; nj++) {
                    mma8(acc[mi][nj], al, bh[nj]);
                    mma8(acc[mi][nj], ah, bl[nj]);
                    mma8(acc[mi][nj], ah, bh[nj]);
                }
            }
        }
    }
#pragma unroll
    for (int mi = 0; mi < 4; mi++)
#pragma unroll
        for (int nj = 0; nj < 4; nj++) {
            int gm = m0 + wm + mi * 16 + r;
            int gn = n0 + wn + nj * 8 + 2 * c;
            *(float2*)&C[(size_t)gm * ldc + gn]       = make_float2(acc[mi][nj].x, acc[mi][nj].y);
            *(float2*)&C[(size_t)(gm + 8) * ldc + gn] = make_float2(acc[mi][nj].z, acc[mi][nj].w);
        }
}

// Fused QKV projection: grid (18, 32)
__global__ void __launch_bounds__(256) gemm_qkv(const float* __restrict__ x,
                                                const float* __restrict__ wq,
                                                const float* __restrict__ wk,
                                                const float* __restrict__ wv,
                                                float* __restrict__ q,
                                                float* __restrict__ k,
                                                float* __restrict__ v) {
    const int nb = blockIdx.x;
    const int sel = nb / 6;
    const int n0 = (nb % 6) * 128;
    const int m0 = blockIdx.y * 128;
    const float* W = (sel == 0) ? wq : (sel == 1) ? wk : wv;
    float* O = (sel == 0) ? q : (sel == 1) ? k : v;
    gemm3_body(x, W, O, C_, C_, C_, C_, m0, n0);
}

// ---------------------------------------------------------------------------
// Final projection, 2-term (A exact hi+lo trunc, B rounded hi): grid (6, 32)
// ---------------------------------------------------------------------------
__global__ void __launch_bounds__(256) gemm_final(const float* __restrict__ A,
                                                  const float* __restrict__ Wo,
                                                  float* __restrict__ C) {
    __shared__ uint2 As[128][SKA];
    __shared__ uint32_t Bs[128][SKA];
    const int m0 = blockIdx.y * 128, n0 = blockIdx.x * 128;
    const int tid = threadIdx.x;
    const int warp = tid >> 5, lane = tid & 31;
    const int wm = (warp >> 2) * 64, wn = (warp & 3) * 32;
    const int r = lane >> 2, c = lane & 3;
    const int row0 = tid >> 2, ko0 = (tid & 3) << 2;
    const int row1 = (tid + 256) >> 2;

    float4 acc[4][4];
#pragma unroll
    for (int i = 0; i < 4; i++)
#pragma unroll
        for (int j = 0; j < 4; j++) acc[i][j] = make_float4(0, 0, 0, 0);

    for (int k0 = 0; k0 < C_; k0 += 16) {
        __syncthreads();
        cvt2t(As, row0, ko0, *(const float4*)(A + (size_t)(m0 + row0) * C_ + k0 + ko0));
        cvt2t(As, row1, ko0, *(const float4*)(A + (size_t)(m0 + row1) * C_ + k0 + ko0));
        cvt1(Bs, row0, ko0, *(const float4*)(Wo + (size_t)(n0 + row0) * C_ + k0 + ko0));
        cvt1(Bs, row1, ko0, *(const float4*)(Wo + (size_t)(n0 + row1) * C_ + k0 + ko0));
        __syncthreads();
#pragma unroll
        for (int kb = 0; kb < 16; kb += 8) {
            uint32_t bh[4][2];
#pragma unroll
            for (int nj = 0; nj < 4; nj++) {
                int col = wn + nj * 8 + r;
                bh[nj][0] = Bs[col][kb + c]; bh[nj][1] = Bs[col][kb + c + 4];
            }
#pragma unroll
            for (int mi = 0; mi < 4; mi++) {
                int rw = wm + mi * 16 + r;
                uint2 a0 = As[rw][kb + c],     a1 = As[rw + 8][kb + c];
                uint2 a2 = As[rw][kb + c + 4], a3 = As[rw + 8][kb + c + 4];
                uint32_t ah[4] = {a0.x, a1.x, a2.x, a3.x};
                uint32_t al[4] = {a0.y, a1.y, a2.y, a3.y};
#pragma unroll
                for (int nj = 0; nj < 4; nj++) {
                    mma8(acc[mi][nj], al, bh[nj]);
                    mma8(acc[mi][nj], ah, bh[nj]);
                }
            }
        }
    }
#pragma unroll
    for (int mi = 0; mi < 4; mi++)
#pragma unroll
        for (int nj = 0; nj < 4; nj++) {
            int gm = m0 + wm + mi * 16 + r;
            int gn = n0 + wn + nj * 8 + 2 * c;
            *(float2*)&C[(size_t)gm * C_ + gn]       = make_float2(acc[mi][nj].x, acc[mi][nj].y);
            *(float2*)&C[(size_t)(gm + 8) * C_ + gn] = make_float2(acc[mi][nj].z, acc[mi][nj].w);
        }
}

// ---------------------------------------------------------------------------
// Scores -> store UNNORMALIZED exp(0.125*QK) (masked->0) + row partial sums.
// 2-term: A = Q exact (hi+lo trunc), B = K rounded hi-only. grid (16, 16, 24)
// ---------------------------------------------------------------------------
__global__ void __launch_bounds__(256) scores_tc(const float* __restrict__ Q,
                                                 const float* __restrict__ Kt,
                                                 float* __restrict__ W,
                                                 float* __restrict__ partial) {
    const int z = blockIdx.z;
    const int b = z / H_, h = z % H_;
    const int m0 = blockIdx.y * 128, n0 = blockIdx.x * 128;
    const int tid = threadIdx.x;
    float* Cz = W + (size_t)z * T_ * T_;

    if (n0 > m0) {  // fully masked tile -> zeros; no partials
        const float4 zz = make_float4(0, 0, 0, 0);
        for (int idx = tid; idx < 128 * 32; idx += 256) {
            int row = idx >> 5, c4 = (idx & 31) << 2;
            *(float4*)&Cz[(size_t)(m0 + row) * T_ + n0 + c4] = zz;
        }
        return;
    }

    __shared__ uint2 As[128][SKA];
    __shared__ uint32_t Bs[128][SKA];
    __shared__ float spart[128][4];
    const int warp = tid >> 5, lane = tid & 31;
    const int wm = (warp >> 2) * 64, wn = (warp & 3) * 32;
    const int r = lane >> 2, c = lane & 3;
    const float* Ap = Q + (size_t)b * T_ * C_ + h * DH_;
    const float* Bp = Kt + (size_t)b * T_ * C_ + h * DH_;
    const int row0 = tid >> 2, ko0 = (tid & 3) << 2;
    const int row1 = (tid + 256) >> 2;

    float4 acc[4][4];
#pragma unroll
    for (int i = 0; i < 4; i++)
#pragma unroll
        for (int j = 0; j < 4; j++) acc[i][j] = make_float4(0, 0, 0, 0);

#pragma unroll
    for (int k0 = 0; k0 < DH_; k0 += 16) {
        __syncthreads();
        cvt2t(As, row0, ko0, *(const float4*)(Ap + (size_t)(m0 + row0) * C_ + k0 + ko0));
        cvt2t(As, row1, ko0, *(const float4*)(Ap + (size_t)(m0 + row1) * C_ + k0 + ko0));
        cvt1(Bs, row0, ko0, *(const float4*)(Bp + (size_t)(n0 + row0) * C_ + k0 + ko0));
        cvt1(Bs, row1, ko0, *(const float4*)(Bp + (size_t)(n0 + row1) * C_ + k0 + ko0));
        __syncthreads();
#pragma unroll
        for (int kb = 0; kb < 16; kb += 8) {
            uint32_t bh[4][2];
#pragma unroll
            for (int nj = 0; nj < 4; nj++) {
                int col = wn + nj * 8 + r;
                bh[nj][0] = Bs[col][kb + c]; bh[nj][1] = Bs[col][kb + c + 4];
            }
#pragma unroll
            for (int mi = 0; mi < 4; mi++) {
                int rw = wm + mi * 16 + r;
                uint2 a0 = As[rw][kb + c],     a1 = As[rw + 8][kb + c];
                uint2 a2 = As[rw][kb + c + 4], a3 = As[rw + 8][kb + c + 4];
                uint32_t ah[4] = {a0.x, a1.x, a2.x, a3.x};
                uint32_t al[4] = {a0.y, a1.y, a2.y, a3.y};
#pragma unroll
                for (int nj = 0; nj < 4; nj++) {
                    mma8(acc[mi][nj], al, bh[nj]);
                    mma8(acc[mi][nj], ah, bh[nj]);
                }
            }
        }
    }

    const bool diag = (n0 == m0);
#pragma unroll
    for (int mi = 0; mi < 4; mi++) {
        float se0 = 0.0f, se1 = 0.0f;
        int gm = m0 + wm + mi * 16 + r;
#pragma unroll
        for (int nj = 0; nj < 4; nj++) {
            int gn = n0 + wn + nj * 8 + 2 * c;
            float e0 = exp2f(0.125f * LOG2E * acc[mi][nj].x);
            float e1 = exp2f(0.125f * LOG2E * acc[mi][nj].y);
            float e2 = exp2f(0.125f * LOG2E * acc[mi][nj].z);
            float e3 = exp2f(0.125f * LOG2E * acc[mi][nj].w);
            if (diag) {
                if (gn > gm) e0 = 0.0f;
                if (gn + 1 > gm) e1 = 0.0f;
                if (gn > gm + 8) e2 = 0.0f;
                if (gn + 1 > gm + 8) e3 = 0.0f;
            }
            se0 += e0 + e1;
            se1 += e2 + e3;
            *(float2*)&Cz[(size_t)gm * T_ + gn]       = make_float2(e0, e1);
            *(float2*)&Cz[(size_t)(gm + 8) * T_ + gn] = make_float2(e2, e3);
        }
        se0 += __shfl_xor_sync(0xffffffffu, se0, 1);
        se0 += __shfl_xor_sync(0xffffffffu, se0, 2);
        se1 += __shfl_xor_sync(0xffffffffu, se1, 1);
        se1 += __shfl_xor_sync(0xffffffffu, se1, 2);
        if (c == 0) {
            spart[wm + mi * 16 + r][warp & 3]     = se0;
            spart[wm + mi * 16 + r + 8][warp & 3] = se1;
        }
    }
    __syncthreads();
    if (tid < 128) {
        float s = spart[tid][0] + spart[tid][1] + spart[tid][2] + spart[tid][3];
        partial[((size_t)z * T_ + m0 + tid) * 16 + (n0 >> 7)] = s;
    }
}

// ---------------------------------------------------------------------------
// Normalize weights in place (computes invsum from partials inline).
// One block (128 thr) per row.
// ---------------------------------------------------------------------------
__global__ void __launch_bounds__(128) normalize_kernel(float* __restrict__ W,
                                                        const float* __restrict__ partial) {
    const int rg = blockIdx.x;
    const int i = rg % T_;
    __shared__ float silv;
    if (threadIdx.x == 0) {
        const float* p = partial + (size_t)rg * 16;
        const int ntmax = i >> 7;
        float s = 0.0f;
        for (int nt = 0; nt <= ntmax; nt++) s += p[nt];
        silv = 1.0f / s;
    }
    __syncthreads();
    const float il = silv;
    const int n4 = (i + 4) >> 2;   // ceil((i+1)/4) float4s (tail zeros scale to 0)
    float4* row = (float4*)(W + (size_t)rg * T_);
    for (int j = threadIdx.x; j < n4; j += 128) {
        float4 v = row[j];
        v.x *= il; v.y *= il; v.z *= il; v.w *= il;
        row[j] = v;
    }
}

// ---------------------------------------------------------------------------
// PV k-split, 2-term (P exact hi+lo trunc, V rounded hi). grid (4, 16, 24).
// ---------------------------------------------------------------------------
__global__ void __launch_bounds__(256) pv_split_tc(const float* __restrict__ W,
                                                   const float* __restrict__ V,
                                                   float* __restrict__ part) {
    const int ck = blockIdx.x;
    const int mt = 15 - blockIdx.y;
    const int z = blockIdx.z;
    const int m0 = mt * 128;
    const int kbeg = ck * 512;
    const int kend = min(kbeg + 512, m0 + 128);
    if (kbeg >= kend) return;

    const int b = z / H_, h = z % H_;
    const int tid = threadIdx.x;
    const int warp = tid >> 5, lane = tid & 31;
    const int wm = (warp >> 2) * 64, wn = (warp & 3) * 16;
    const int r = lane >> 2, c = lane & 3;

    const float* Wz = W + (size_t)z * T_ * T_;
    const float* Vp = V + (size_t)b * T_ * C_ + h * DH_;

    __shared__ uint2 As[128][SKA];
    __shared__ uint32_t Bs[64][SKA];

    const int row0 = tid >> 2, ko0 = (tid & 3) << 2;
    const int row1 = (tid + 256) >> 2;
    const int kr = tid >> 4, nc = (tid & 15) << 2;

    float4 acc[4][2];
#pragma unroll
    for (int i = 0; i < 4; i++)
#pragma unroll
        for (int j = 0; j < 2; j++) acc[i][j] = make_float4(0, 0, 0, 0);

    for (int k0 = kbeg; k0 < kend; k0 += 16) {
        __syncthreads();
        cvt2t(As, row0, ko0, *(const float4*)(Wz + (size_t)(m0 + row0) * T_ + k0 + ko0));
        cvt2t(As, row1, ko0, *(const float4*)(Wz + (size_t)(m0 + row1) * T_ + k0 + ko0));
        {
            float4 v = *(const float4*)(Vp + (size_t)(k0 + kr) * C_ + nc);
            Bs[nc + 0][kr] = f2tf(v.x);
            Bs[nc + 1][kr] = f2tf(v.y);
            Bs[nc + 2][kr] = f2tf(v.z);
            Bs[nc + 3][kr] = f2tf(v.w);
        }
        __syncthreads();
#pragma unroll
        for (int kb = 0; kb < 16; kb += 8) {
            uint32_t bh[2][2];
#pragma unroll
            for (int nj = 0; nj < 2; nj++) {
                int col = wn + nj * 8 + r;
                bh[nj][0] = Bs[col][kb + c]; bh[nj][1] = Bs[col][kb + c + 4];
            }
#pragma unroll
            for (int mi = 0; mi < 4; mi++) {
                int rw = wm + mi * 16 + r;
                uint2 a0 = As[rw][kb + c],     a1 = As[rw + 8][kb + c];
                uint2 a2 = As[rw][kb + c + 4], a3 = As[rw + 8][kb + c + 4];
                uint32_t ah[4] = {a0.x, a1.x, a2.x, a3.x};
                uint32_t al[4] = {a0.y, a1.y, a2.y, a3.y};
#pragma unroll
                for (int nj = 0; nj < 2; nj++) {
                    mma8(acc[mi][nj], al, bh[nj]);
                    mma8(acc[mi][nj], ah, bh[nj]);
                }
            }
        }
    }

    float* P = part + ((size_t)(z * 16 + mt) * 4 + ck) * (128 * DH_);
#pragma unroll
    for (int mi = 0; mi < 4; mi++)
#pragma unroll
        for (int nj = 0; nj < 2; nj++) {
            int lr = wm + mi * 16 + r;
            int gn = wn + nj * 8 + 2 * c;
            *(float2*)&P[(size_t)lr * DH_ + gn]       = make_float2(acc[mi][nj].x, acc[mi][nj].y);
            *(float2*)&P[(size_t)(lr + 8) * DH_ + gn] = make_float2(acc[mi][nj].z, acc[mi][nj].w);
        }
}

// ---------------------------------------------------------------------------
// Sum pv partials -> O (g_att layout [B,T,C]). grid (384), 256 thr.
// ---------------------------------------------------------------------------
__global__ void __launch_bounds__(256) pv_reduce(const float* __restrict__ part,
                                                 float* __restrict__ O) {
    const int blk = blockIdx.x;            // z*16 + mt
    const int z = blk >> 4, mt = blk & 15;
    const int b = z / H_, h = z % H_;
    const int m0 = mt * 128;
    const int nch = (mt >> 2) + 1;         // ceil((mt+1)*128/512)
    const float* p = part + (size_t)blk * 4 * (128 * DH_);

    for (int idx = threadIdx.x * 4; idx < 128 * DH_; idx += 256 * 4) {
        float4 s = *(const float4*)(p + idx);
        for (int c2 = 1; c2 < nch; c2++) {
            float4 t = *(const float4*)(p + (size_t)c2 * 128 * DH_ + idx);
            s.x += t.x; s.y += t.y; s.z += t.z; s.w += t.w;
        }
        const int row = idx >> 6, n = idx & 63;
        *(float4*)&O[(size_t)(b * T_ + m0 + row) * C_ + h * DH_ + n] = s;
    }
}

// ---------------------------------------------------------------------------
extern "C" void kernel_launch(void* const* d_in, const int* in_sizes, int n_in,
                              void* d_out, int out_size) {
    const float* x   = (const float*)d_in[0];
    const float* w_q = (const float*)d_in[1];
    const float* w_k = (const float*)d_in[2];
    const float* w_v = (const float*)d_in[3];
    const float* w_o = (const float*)d_in[4];

    float* qp; cudaGetSymbolAddress((void**)&qp, g_q);
    float* kp; cudaGetSymbolAddress((void**)&kp, g_k);
    float* vp; cudaGetSymbolAddress((void**)&vp, g_v);
    float* ap; cudaGetSymbolAddress((void**)&ap, g_att);
    float* pp; cudaGetSymbolAddress((void**)&pp, g_partial);
    float* vv; cudaGetSymbolAddress((void**)&vv, g_pvpart);

    float* final_out = (float*)d_out;                       // [B,T,C]
    float* w_out = (float*)d_out + (size_t)B_ * T_ * C_;    // [B,H,T,T]

    const dim3 blk(256);

    gemm_qkv<<<dim3(18, 32), blk>>>(x, w_q, w_k, w_v, qp, kp, vp);

    scores_tc<<<dim3(T_ / 128, T_ / 128, B_ * H_), blk>>>(qp, kp, w_out, pp);

    normalize_kernel<<<B_ * H_ * T_, 128>>>(w_out, pp);

    pv_split_tc<<<dim3(4, 16, 24), blk>>>(w_out, vp, vv);

    pv_reduce<<<B_ * H_ * 16, blk>>>(vv, ap);

    gemm_final<<<dim3(6, 32), blk>>>(ap, w_o, final_out);
}

// round 12
// speedup vs baseline: 1.6291x; 1.3563x over previous
#include <cuda_runtime.h>
#include <math.h>
#include <stdint.h>

#define B_   2
#define T_   2048
#define C_   768
#define H_   12
#define DH_  64
#define LOG2E 1.4426950408889634f
#define SKF  20   // float row stride (16 data + 4 pad) -> conflict-free frag LDS
#define SVF  72   // V k-major row stride (64 data + 8 pad)

// Scratch (device globals — no allocation allowed)
__device__ float g_q[B_ * T_ * C_];
__device__ float g_k[B_ * T_ * C_];
__device__ float g_v[B_ * T_ * C_];
__device__ float g_att[B_ * T_ * C_];
__device__ float g_partial[B_ * H_ * T_ * 16];      // per (row, colTile) partial sum(exp)
__device__ float g_pvpart[B_ * H_ * 16 * 4 * 128 * DH_];  // pv k-split partials

// ---------------------------------------------------------------------------
__device__ __forceinline__ uint32_t f2tf(float v) {   // rounded tf32
    uint32_t r;
    asm("cvt.rna.tf32.f32 %0, %1;" : "=r"(r) : "f"(v));
    return r;
}
__device__ __forceinline__ void mma8(float4& d, const uint32_t* a, const uint32_t* b) {
    asm("mma.sync.aligned.m16n8k8.row.col.f32.tf32.tf32.f32 "
        "{%0,%1,%2,%3}, {%4,%5,%6,%7}, {%8,%9}, {%0,%1,%2,%3};"
        : "+f"(d.x), "+f"(d.y), "+f"(d.z), "+f"(d.w)
        : "r"(a[0]), "r"(a[1]), "r"(a[2]), "r"(a[3]), "r"(b[0]), "r"(b[1]));
}
// consumer-side exact split: hi = raw fp32 bits (HW reads top 19), lo exact.
__device__ __forceinline__ void split_lo(float v, uint32_t& hi, uint32_t& lo) {
    hi = __float_as_uint(v);
    lo = __float_as_uint(v - __uint_as_float(hi & 0xFFFFE000u));
}
__device__ __forceinline__ void cp16(void* smem_dst, const void* gsrc) {
    uint32_t s = (uint32_t)__cvta_generic_to_shared(smem_dst);
    asm volatile("cp.async.cg.shared.global [%0], [%1], 16;" :: "r"(s), "l"(gsrc));
}
#define CP_COMMIT asm volatile("cp.async.commit_group;")
#define CP_WAIT1  asm volatile("cp.async.wait_group 1;")
#define CP_WAIT0  asm volatile("cp.async.wait_group 0;")

// ---------------------------------------------------------------------------
// 3-term NT GEMM (QKV path): cp.async double buffer, consumer-side split.
// ---------------------------------------------------------------------------
__device__ __forceinline__ void gemm3_body(const float* __restrict__ A,
                                           const float* __restrict__ Bm,
                                           float* __restrict__ C,
                                           int K, int lda, int ldb, int ldc,
                                           int m0, int n0) {
    __shared__ float As[2][128][SKF], Bs[2][128][SKF];
    const int tid = threadIdx.x;
    const int warp = tid >> 5, lane = tid & 31;
    const int wm = (warp >> 2) * 64, wn = (warp & 3) * 32;
    const int r = lane >> 2, c = lane & 3;
    const int row0 = tid >> 2, ko0 = (tid & 3) << 2;
    const int row1 = row0 + 64;

    float4 acc[4][4];
#pragma unroll
    for (int i = 0; i < 4; i++)
#pragma unroll
        for (int j = 0; j < 4; j++) acc[i][j] = make_float4(0, 0, 0, 0);

    const int niter = K / 16;
    // preload stage 0
    cp16(&As[0][row0][ko0], A + (size_t)(m0 + row0) * lda + ko0);
    cp16(&As[0][row1][ko0], A + (size_t)(m0 + row1) * lda + ko0);
    cp16(&Bs[0][row0][ko0], Bm + (size_t)(n0 + row0) * ldb + ko0);
    cp16(&Bs[0][row1][ko0], Bm + (size_t)(n0 + row1) * ldb + ko0);
    CP_COMMIT;

    for (int it = 0; it < niter; it++) {
        if (it + 1 < niter) {
            int kn = (it + 1) * 16;
            int s = (it + 1) & 1;
            cp16(&As[s][row0][ko0], A + (size_t)(m0 + row0) * lda + kn + ko0);
            cp16(&As[s][row1][ko0], A + (size_t)(m0 + row1) * lda + kn + ko0);
            cp16(&Bs[s][row0][ko0], Bm + (size_t)(n0 + row0) * ldb + kn + ko0);
            cp16(&Bs[s][row1][ko0], Bm + (size_t)(n0 + row1) * ldb + kn + ko0);
            CP_COMMIT;
            CP_WAIT1;
        } else {
            CP_WAIT0;
        }
        __syncthreads();
        const float (*Af)[SKF] = As[it & 1];
        const float (*Bf)[SKF] = Bs[it & 1];
#pragma unroll
        for (int kb = 0; kb < 16; kb += 8) {
            uint32_t bh[4][2], bl[4][2];
#pragma unroll
            for (int nj = 0; nj < 4; nj++) {
                int col = wn + nj * 8 + r;
                split_lo(Bf[col][kb + c],     bh[nj][0], bl[nj][0]);
                split_lo(Bf[col][kb + c + 4], bh[nj][1], bl[nj][1]);
            }
#pragma unroll
            for (int mi = 0; mi < 4; mi++) {
                int rw = wm + mi * 16 + r;
                uint32_t ah[4], al[4];
                split_lo(Af[rw][kb + c],         ah[0], al[0]);
                split_lo(Af[rw + 8][kb + c],     ah[1], al[1]);
                split_lo(Af[rw][kb + c + 4],     ah[2], al[2]);
                split_lo(Af[rw + 8][kb + c + 4], ah[3], al[3]);
#pragma unroll
                for (int nj = 0; nj < 4; nj++) {
                    mma8(acc[mi][nj], al, bh[nj]);
                    mma8(acc[mi][nj], ah, bl[nj]);
                    mma8(acc[mi][nj], ah, bh[nj]);
                }
            }
        }
        __syncthreads();
    }
#pragma unroll
    for (int mi = 0; mi < 4; mi++)
#pragma unroll
        for (int nj = 0; nj < 4; nj++) {
            int gm = m0 + wm + mi * 16 + r;
            int gn = n0 + wn + nj * 8 + 2 * c;
            *(float2*)&C[(size_t)gm * ldc + gn]       = make_float2(acc[mi][nj].x, acc[mi][nj].y);
            *(float2*)&C[(size_t)(gm + 8) * ldc + gn] = make_float2(acc[mi][nj].z, acc[mi][nj].w);
        }
}

// Fused QKV projection: grid (18, 32)
__global__ void __launch_bounds__(256) gemm_qkv(const float* __restrict__ x,
                                                const float* __restrict__ wq,
                                                const float* __restrict__ wk,
                                                const float* __restrict__ wv,
                                                float* __restrict__ q,
                                                float* __restrict__ k,
                                                float* __restrict__ v) {
    const int nb = blockIdx.x;
    const int sel = nb / 6;
    const int n0 = (nb % 6) * 128;
    const int m0 = blockIdx.y * 128;
    const float* W = (sel == 0) ? wq : (sel == 1) ? wk : wv;
    float* O = (sel == 0) ? q : (sel == 1) ? k : v;
    gemm3_body(x, W, O, C_, C_, C_, C_, m0, n0);
}

// ---------------------------------------------------------------------------
// Final projection, 2-term (A exact split, B rounded): grid (6, 32)
// ---------------------------------------------------------------------------
__global__ void __launch_bounds__(256) gemm_final(const float* __restrict__ A,
                                                  const float* __restrict__ Wo,
                                                  float* __restrict__ C) {
    __shared__ float As[2][128][SKF], Bs[2][128][SKF];
    const int m0 = blockIdx.y * 128, n0 = blockIdx.x * 128;
    const int tid = threadIdx.x;
    const int warp = tid >> 5, lane = tid & 31;
    const int wm = (warp >> 2) * 64, wn = (warp & 3) * 32;
    const int r = lane >> 2, c = lane & 3;
    const int row0 = tid >> 2, ko0 = (tid & 3) << 2;
    const int row1 = row0 + 64;

    float4 acc[4][4];
#pragma unroll
    for (int i = 0; i < 4; i++)
#pragma unroll
        for (int j = 0; j < 4; j++) acc[i][j] = make_float4(0, 0, 0, 0);

    const int niter = C_ / 16;
    cp16(&As[0][row0][ko0], A + (size_t)(m0 + row0) * C_ + ko0);
    cp16(&As[0][row1][ko0], A + (size_t)(m0 + row1) * C_ + ko0);
    cp16(&Bs[0][row0][ko0], Wo + (size_t)(n0 + row0) * C_ + ko0);
    cp16(&Bs[0][row1][ko0], Wo + (size_t)(n0 + row1) * C_ + ko0);
    CP_COMMIT;

    for (int it = 0; it < niter; it++) {
        if (it + 1 < niter) {
            int kn = (it + 1) * 16;
            int s = (it + 1) & 1;
            cp16(&As[s][row0][ko0], A + (size_t)(m0 + row0) * C_ + kn + ko0);
            cp16(&As[s][row1][ko0], A + (size_t)(m0 + row1) * C_ + kn + ko0);
            cp16(&Bs[s][row0][ko0], Wo + (size_t)(n0 + row0) * C_ + kn + ko0);
            cp16(&Bs[s][row1][ko0], Wo + (size_t)(n0 + row1) * C_ + kn + ko0);
            CP_COMMIT;
            CP_WAIT1;
        } else {
            CP_WAIT0;
        }
        __syncthreads();
        const float (*Af)[SKF] = As[it & 1];
        const float (*Bf)[SKF] = Bs[it & 1];
#pragma unroll
        for (int kb = 0; kb < 16; kb += 8) {
            uint32_t bh[4][2];
#pragma unroll
            for (int nj = 0; nj < 4; nj++) {
                int col = wn + nj * 8 + r;
                bh[nj][0] = f2tf(Bf[col][kb + c]);
                bh[nj][1] = f2tf(Bf[col][kb + c + 4]);
            }
#pragma unroll
            for (int mi = 0; mi < 4; mi++) {
                int rw = wm + mi * 16 + r;
                uint32_t ah[4], al[4];
                split_lo(Af[rw][kb + c],         ah[0], al[0]);
                split_lo(Af[rw + 8][kb + c],     ah[1], al[1]);
                split_lo(Af[rw][kb + c + 4],     ah[2], al[2]);
                split_lo(Af[rw + 8][kb + c + 4], ah[3], al[3]);
#pragma unroll
                for (int nj = 0; nj < 4; nj++) {
                    mma8(acc[mi][nj], al, bh[nj]);
                    mma8(acc[mi][nj], ah, bh[nj]);
                }
            }
        }
        __syncthreads();
    }
#pragma unroll
    for (int mi = 0; mi < 4; mi++)
#pragma unroll
        for (int nj = 0; nj < 4; nj++) {
            int gm = m0 + wm + mi * 16 + r;
            int gn = n0 + wn + nj * 8 + 2 * c;
            *(float2*)&C[(size_t)gm * C_ + gn]       = make_float2(acc[mi][nj].x, acc[mi][nj].y);
            *(float2*)&C[(size_t)(gm + 8) * C_ + gn] = make_float2(acc[mi][nj].z, acc[mi][nj].w);
        }
}

// ---------------------------------------------------------------------------
// Scores -> store UNNORMALIZED exp(0.125*QK) (masked->0) + row partial sums.
// 2-term. grid (16, 16, 24)
// ---------------------------------------------------------------------------
__global__ void __launch_bounds__(256) scores_tc(const float* __restrict__ Q,
                                                 const float* __restrict__ Kt,
                                                 float* __restrict__ W,
                                                 float* __restrict__ partial) {
    const int z = blockIdx.z;
    const int b = z / H_, h = z % H_;
    const int m0 = blockIdx.y * 128, n0 = blockIdx.x * 128;
    const int tid = threadIdx.x;
    float* Cz = W + (size_t)z * T_ * T_;

    if (n0 > m0) {  // fully masked tile -> zeros; no partials
        const float4 zz = make_float4(0, 0, 0, 0);
        for (int idx = tid; idx < 128 * 32; idx += 256) {
            int row = idx >> 5, c4 = (idx & 31) << 2;
            *(float4*)&Cz[(size_t)(m0 + row) * T_ + n0 + c4] = zz;
        }
        return;
    }

    __shared__ float As[2][128][SKF], Bs[2][128][SKF];
    __shared__ float spart[128][4];
    const int warp = tid >> 5, lane = tid & 31;
    const int wm = (warp >> 2) * 64, wn = (warp & 3) * 32;
    const int r = lane >> 2, c = lane & 3;
    const float* Ap = Q + (size_t)b * T_ * C_ + h * DH_;
    const float* Bp = Kt + (size_t)b * T_ * C_ + h * DH_;
    const int row0 = tid >> 2, ko0 = (tid & 3) << 2;
    const int row1 = row0 + 64;

    float4 acc[4][4];
#pragma unroll
    for (int i = 0; i < 4; i++)
#pragma unroll
        for (int j = 0; j < 4; j++) acc[i][j] = make_float4(0, 0, 0, 0);

    cp16(&As[0][row0][ko0], Ap + (size_t)(m0 + row0) * C_ + ko0);
    cp16(&As[0][row1][ko0], Ap + (size_t)(m0 + row1) * C_ + ko0);
    cp16(&Bs[0][row0][ko0], Bp + (size_t)(n0 + row0) * C_ + ko0);
    cp16(&Bs[0][row1][ko0], Bp + (size_t)(n0 + row1) * C_ + ko0);
    CP_COMMIT;

#pragma unroll
    for (int it = 0; it < DH_ / 16; it++) {
        if (it + 1 < DH_ / 16) {
            int kn = (it + 1) * 16;
            int s = (it + 1) & 1;
            cp16(&As[s][row0][ko0], Ap + (size_t)(m0 + row0) * C_ + kn + ko0);
            cp16(&As[s][row1][ko0], Ap + (size_t)(m0 + row1) * C_ + kn + ko0);
            cp16(&Bs[s][row0][ko0], Bp + (size_t)(n0 + row0) * C_ + kn + ko0);
            cp16(&Bs[s][row1][ko0], Bp + (size_t)(n0 + row1) * C_ + kn + ko0);
            CP_COMMIT;
            CP_WAIT1;
        } else {
            CP_WAIT0;
        }
        __syncthreads();
        const float (*Af)[SKF] = As[it & 1];
        const float (*Bf)[SKF] = Bs[it & 1];
#pragma unroll
        for (int kb = 0; kb < 16; kb += 8) {
            uint32_t bh[4][2];
#pragma unroll
            for (int nj = 0; nj < 4; nj++) {
                int col = wn + nj * 8 + r;
                bh[nj][0] = f2tf(Bf[col][kb + c]);
                bh[nj][1] = f2tf(Bf[col][kb + c + 4]);
            }
#pragma unroll
            for (int mi = 0; mi < 4; mi++) {
                int rw = wm + mi * 16 + r;
                uint32_t ah[4], al[4];
                split_lo(Af[rw][kb + c],         ah[0], al[0]);
                split_lo(Af[rw + 8][kb + c],     ah[1], al[1]);
                split_lo(Af[rw][kb + c + 4],     ah[2], al[2]);
                split_lo(Af[rw + 8][kb + c + 4], ah[3], al[3]);
#pragma unroll
                for (int nj = 0; nj < 4; nj++) {
                    mma8(acc[mi][nj], al, bh[nj]);
                    mma8(acc[mi][nj], ah, bh[nj]);
                }
            }
        }
        __syncthreads();
    }

    const bool diag = (n0 == m0);
#pragma unroll
    for (int mi = 0; mi < 4; mi++) {
        float se0 = 0.0f, se1 = 0.0f;
        int gm = m0 + wm + mi * 16 + r;
#pragma unroll
        for (int nj = 0; nj < 4; nj++) {
            int gn = n0 + wn + nj * 8 + 2 * c;
            float e0 = exp2f(0.125f * LOG2E * acc[mi][nj].x);
            float e1 = exp2f(0.125f * LOG2E * acc[mi][nj].y);
            float e2 = exp2f(0.125f * LOG2E * acc[mi][nj].z);
            float e3 = exp2f(0.125f * LOG2E * acc[mi][nj].w);
            if (diag) {
                if (gn > gm) e0 = 0.0f;
                if (gn + 1 > gm) e1 = 0.0f;
                if (gn > gm + 8) e2 = 0.0f;
                if (gn + 1 > gm + 8) e3 = 0.0f;
            }
            se0 += e0 + e1;
            se1 += e2 + e3;
            *(float2*)&Cz[(size_t)gm * T_ + gn]       = make_float2(e0, e1);
            *(float2*)&Cz[(size_t)(gm + 8) * T_ + gn] = make_float2(e2, e3);
        }
        se0 += __shfl_xor_sync(0xffffffffu, se0, 1);
        se0 += __shfl_xor_sync(0xffffffffu, se0, 2);
        se1 += __shfl_xor_sync(0xffffffffu, se1, 1);
        se1 += __shfl_xor_sync(0xffffffffu, se1, 2);
        if (c == 0) {
            spart[wm + mi * 16 + r][warp & 3]     = se0;
            spart[wm + mi * 16 + r + 8][warp & 3] = se1;
        }
    }
    __syncthreads();
    if (tid < 128) {
        float s = spart[tid][0] + spart[tid][1] + spart[tid][2] + spart[tid][3];
        partial[((size_t)z * T_ + m0 + tid) * 16 + (n0 >> 7)] = s;
    }
}

// ---------------------------------------------------------------------------
// Normalize weights in place (computes invsum from partials inline).
// ---------------------------------------------------------------------------
__global__ void __launch_bounds__(128) normalize_kernel(float* __restrict__ W,
                                                        const float* __restrict__ partial) {
    const int rg = blockIdx.x;
    const int i = rg % T_;
    __shared__ float silv;
    if (threadIdx.x == 0) {
        const float* p = partial + (size_t)rg * 16;
        const int ntmax = i >> 7;
        float s = 0.0f;
        for (int nt = 0; nt <= ntmax; nt++) s += p[nt];
        silv = 1.0f / s;
    }
    __syncthreads();
    const float il = silv;
    const int n4 = (i + 4) >> 2;
    float4* row = (float4*)(W + (size_t)rg * T_);
    for (int j = threadIdx.x; j < n4; j += 128) {
        float4 v = row[j];
        v.x *= il; v.y *= il; v.z *= il; v.w *= il;
        row[j] = v;
    }
}

// ---------------------------------------------------------------------------
// PV k-split, 2-term. V stored k-major [16][SVF]. grid (4, 16, 24).
// ---------------------------------------------------------------------------
__global__ void __launch_bounds__(256) pv_split_tc(const float* __restrict__ W,
                                                   const float* __restrict__ V,
                                                   float* __restrict__ part) {
    const int ck = blockIdx.x;
    const int mt = 15 - blockIdx.y;
    const int z = blockIdx.z;
    const int m0 = mt * 128;
    const int kbeg = ck * 512;
    const int kend = min(kbeg + 512, m0 + 128);
    if (kbeg >= kend) return;

    const int b = z / H_, h = z % H_;
    const int tid = threadIdx.x;
    const int warp = tid >> 5, lane = tid & 31;
    const int wm = (warp >> 2) * 64, wn = (warp & 3) * 16;
    const int r = lane >> 2, c = lane & 3;

    const float* Wz = W + (size_t)z * T_ * T_;
    const float* Vp = V + (size_t)b * T_ * C_ + h * DH_;

    __shared__ float As[2][128][SKF];
    __shared__ float Vs[2][16][SVF];

    const int row0 = tid >> 2, ko0 = (tid & 3) << 2;
    const int row1 = row0 + 64;
    const int kr = tid >> 4, nc = (tid & 15) << 2;

    float4 acc[4][2];
#pragma unroll
    for (int i = 0; i < 4; i++)
#pragma unroll
        for (int j = 0; j < 2; j++) acc[i][j] = make_float4(0, 0, 0, 0);

    const int niter = (kend - kbeg) / 16;
    cp16(&As[0][row0][ko0], Wz + (size_t)(m0 + row0) * T_ + kbeg + ko0);
    cp16(&As[0][row1][ko0], Wz + (size_t)(m0 + row1) * T_ + kbeg + ko0);
    cp16(&Vs[0][kr][nc],    Vp + (size_t)(kbeg + kr) * C_ + nc);
    CP_COMMIT;

    for (int it = 0; it < niter; it++) {
        if (it + 1 < niter) {
            int kn = kbeg + (it + 1) * 16;
            int s = (it + 1) & 1;
            cp16(&As[s][row0][ko0], Wz + (size_t)(m0 + row0) * T_ + kn + ko0);
            cp16(&As[s][row1][ko0], Wz + (size_t)(m0 + row1) * T_ + kn + ko0);
            cp16(&Vs[s][kr][nc],    Vp + (size_t)(kn + kr) * C_ + nc);
            CP_COMMIT;
            CP_WAIT1;
        } else {
            CP_WAIT0;
        }
        __syncthreads();
        const float (*Af)[SKF] = As[it & 1];
        const float (*Vf)[SVF] = Vs[it & 1];
#pragma unroll
        for (int kb = 0; kb < 16; kb += 8) {
            uint32_t bh[2][2];
#pragma unroll
            for (int nj = 0; nj < 2; nj++) {
                int col = wn + nj * 8 + r;
                bh[nj][0] = f2tf(Vf[kb + c][col]);
                bh[nj][1] = f2tf(Vf[kb + c + 4][col]);
            }
#pragma unroll
            for (int mi = 0; mi < 4; mi++) {
                int rw = wm + mi * 16 + r;
                uint32_t ah[4], al[4];
                split_lo(Af[rw][kb + c],         ah[0], al[0]);
                split_lo(Af[rw + 8][kb + c],     ah[1], al[1]);
                split_lo(Af[rw][kb + c + 4],     ah[2], al[2]);
                split_lo(Af[rw + 8][kb + c + 4], ah[3], al[3]);
#pragma unroll
                for (int nj = 0; nj < 2; nj++) {
                    mma8(acc[mi][nj], al, bh[nj]);
                    mma8(acc[mi][nj], ah, bh[nj]);
                }
            }
        }
        __syncthreads();
    }

    float* P = part + ((size_t)(z * 16 + mt) * 4 + ck) * (128 * DH_);
#pragma unroll
    for (int mi = 0; mi < 4; mi++)
#pragma unroll
        for (int nj = 0; nj < 2; nj++) {
            int lr = wm + mi * 16 + r;
            int gn = wn + nj * 8 + 2 * c;
            *(float2*)&P[(size_t)lr * DH_ + gn]       = make_float2(acc[mi][nj].x, acc[mi][nj].y);
            *(float2*)&P[(size_t)(lr + 8) * DH_ + gn] = make_float2(acc[mi][nj].z, acc[mi][nj].w);
        }
}

// ---------------------------------------------------------------------------
// Sum pv partials -> O (g_att layout [B,T,C]). grid (384), 256 thr.
// ---------------------------------------------------------------------------
__global__ void __launch_bounds__(256) pv_reduce(const float* __restrict__ part,
                                                 float* __restrict__ O) {
    const int blk = blockIdx.x;            // z*16 + mt
    const int z = blk >> 4, mt = blk & 15;
    const int b = z / H_, h = z % H_;
    const int m0 = mt * 128;
    const int nch = (mt >> 2) + 1;
    const float* p = part + (size_t)blk * 4 * (128 * DH_);

    for (int idx = threadIdx.x * 4; idx < 128 * DH_; idx += 256 * 4) {
        float4 s = *(const float4*)(p + idx);
        for (int c2 = 1; c2 < nch; c2++) {
            float4 t = *(const float4*)(p + (size_t)c2 * 128 * DH_ + idx);
            s.x += t.x; s.y += t.y; s.z += t.z; s.w += t.w;
        }
        const int row = idx >> 6, n = idx & 63;
        *(float4*)&O[(size_t)(b * T_ + m0 + row) * C_ + h * DH_ + n] = s;
    }
}

// ---------------------------------------------------------------------------
extern "C" void kernel_launch(void* const* d_in, const int* in_sizes, int n_in,
                              void* d_out, int out_size) {
    const float* x   = (const float*)d_in[0];
    const float* w_q = (const float*)d_in[1];
    const float* w_k = (const float*)d_in[2];
    const float* w_v = (const float*)d_in[3];
    const float* w_o = (const float*)d_in[4];

    float* qp; cudaGetSymbolAddress((void**)&qp, g_q);
    float* kp; cudaGetSymbolAddress((void**)&kp, g_k);
    float* vp; cudaGetSymbolAddress((void**)&vp, g_v);
    float* ap; cudaGetSymbolAddress((void**)&ap, g_att);
    float* pp; cudaGetSymbolAddress((void**)&pp, g_partial);
    float* vv; cudaGetSymbolAddress((void**)&vv, g_pvpart);

    float* final_out = (float*)d_out;                       // [B,T,C]
    float* w_out = (float*)d_out + (size_t)B_ * T_ * C_;    // [B,H,T,T]

    const dim3 blk(256);

    gemm_qkv<<<dim3(18, 32), blk>>>(x, w_q, w_k, w_v, qp, kp, vp);

    scores_tc<<<dim3(T_ / 128, T_ / 128, B_ * H_), blk>>>(qp, kp, w_out, pp);

    normalize_kernel<<<B_ * H_ * T_, 128>>>(w_out, pp);

    pv_split_tc<<<dim3(4, 16, 24), blk>>>(w_out, vp, vv);

    pv_reduce<<<B_ * H_ * 16, blk>>>(vv, ap);

    gemm_final<<<dim3(6, 32), blk>>>(ap, w_o, final_out);
}

// round 13
// speedup vs baseline: 1.7610x; 1.0809x over previous
#include <cuda_runtime.h>
#include <math.h>
#include <stdint.h>

#define B_   2
#define T_   2048
#define C_   768
#define H_   12
#define DH_  64
#define LOG2E 1.4426950408889634f
#define SKF  20   // float row stride (16 data + 4 pad) -> conflict-free frag LDS
#define SVF  72   // V k-major row stride (64 data + 8 pad)

// Scratch (device globals — no allocation allowed)
__device__ float g_q[B_ * T_ * C_];
__device__ float g_k[B_ * T_ * C_];
__device__ float g_v[B_ * T_ * C_];
__device__ float g_att[B_ * T_ * C_];
__device__ float g_partial[B_ * H_ * T_ * 16];      // per (row, colTile) partial sum(exp)
__device__ float g_pvpart[B_ * H_ * 16 * 4 * 128 * DH_];  // pv k-split partials

// ---------------------------------------------------------------------------
__device__ __forceinline__ uint32_t f2tf(float v) {   // rounded tf32
    uint32_t r;
    asm("cvt.rna.tf32.f32 %0, %1;" : "=r"(r) : "f"(v));
    return r;
}
__device__ __forceinline__ void mma8(float4& d, const uint32_t* a, const uint32_t* b) {
    asm("mma.sync.aligned.m16n8k8.row.col.f32.tf32.tf32.f32 "
        "{%0,%1,%2,%3}, {%4,%5,%6,%7}, {%8,%9}, {%0,%1,%2,%3};"
        : "+f"(d.x), "+f"(d.y), "+f"(d.z), "+f"(d.w)
        : "r"(a[0]), "r"(a[1]), "r"(a[2]), "r"(a[3]), "r"(b[0]), "r"(b[1]));
}
// consumer-side exact split: hi = raw fp32 bits (HW reads top 19), lo exact.
__device__ __forceinline__ void split_lo(float v, uint32_t& hi, uint32_t& lo) {
    hi = __float_as_uint(v);
    lo = __float_as_uint(v - __uint_as_float(hi & 0xFFFFE000u));
}
__device__ __forceinline__ void cp16(void* smem_dst, const void* gsrc) {
    uint32_t s = (uint32_t)__cvta_generic_to_shared(smem_dst);
    asm volatile("cp.async.cg.shared.global [%0], [%1], 16;" :: "r"(s), "l"(gsrc));
}
#define CP_COMMIT asm volatile("cp.async.commit_group;")
#define CP_WAIT1  asm volatile("cp.async.wait_group 1;")
#define CP_WAIT0  asm volatile("cp.async.wait_group 0;")

// ---------------------------------------------------------------------------
// 2-term NT GEMM (A exact hi+lo split, B rounded hi-only), cp.async pipeline.
// Used by QKV and final projections.
// ---------------------------------------------------------------------------
__device__ __forceinline__ void gemm2_body(const float* __restrict__ A,
                                           const float* __restrict__ Bm,
                                           float* __restrict__ C,
                                           int K, int lda, int ldb, int ldc,
                                           int m0, int n0) {
    __shared__ float As[2][128][SKF], Bs[2][128][SKF];
    const int tid = threadIdx.x;
    const int warp = tid >> 5, lane = tid & 31;
    const int wm = (warp >> 2) * 64, wn = (warp & 3) * 32;
    const int r = lane >> 2, c = lane & 3;
    const int row0 = tid >> 2, ko0 = (tid & 3) << 2;
    const int row1 = row0 + 64;

    float4 acc[4][4];
#pragma unroll
    for (int i = 0; i < 4; i++)
#pragma unroll
        for (int j = 0; j < 4; j++) acc[i][j] = make_float4(0, 0, 0, 0);

    const int niter = K / 16;
    cp16(&As[0][row0][ko0], A + (size_t)(m0 + row0) * lda + ko0);
    cp16(&As[0][row1][ko0], A + (size_t)(m0 + row1) * lda + ko0);
    cp16(&Bs[0][row0][ko0], Bm + (size_t)(n0 + row0) * ldb + ko0);
    cp16(&Bs[0][row1][ko0], Bm + (size_t)(n0 + row1) * ldb + ko0);
    CP_COMMIT;

    for (int it = 0; it < niter; it++) {
        if (it + 1 < niter) {
            int kn = (it + 1) * 16;
            int s = (it + 1) & 1;
            cp16(&As[s][row0][ko0], A + (size_t)(m0 + row0) * lda + kn + ko0);
            cp16(&As[s][row1][ko0], A + (size_t)(m0 + row1) * lda + kn + ko0);
            cp16(&Bs[s][row0][ko0], Bm + (size_t)(n0 + row0) * ldb + kn + ko0);
            cp16(&Bs[s][row1][ko0], Bm + (size_t)(n0 + row1) * ldb + kn + ko0);
            CP_COMMIT;
            CP_WAIT1;
        } else {
            CP_WAIT0;
        }
        __syncthreads();
        const float (*Af)[SKF] = As[it & 1];
        const float (*Bf)[SKF] = Bs[it & 1];
#pragma unroll
        for (int kb = 0; kb < 16; kb += 8) {
            uint32_t bh[4][2];
#pragma unroll
            for (int nj = 0; nj < 4; nj++) {
                int col = wn + nj * 8 + r;
                bh[nj][0] = f2tf(Bf[col][kb + c]);
                bh[nj][1] = f2tf(Bf[col][kb + c + 4]);
            }
#pragma unroll
            for (int mi = 0; mi < 4; mi++) {
                int rw = wm + mi * 16 + r;
                uint32_t ah[4], al[4];
                split_lo(Af[rw][kb + c],         ah[0], al[0]);
                split_lo(Af[rw + 8][kb + c],     ah[1], al[1]);
                split_lo(Af[rw][kb + c + 4],     ah[2], al[2]);
                split_lo(Af[rw + 8][kb + c + 4], ah[3], al[3]);
#pragma unroll
                for (int nj = 0; nj < 4; nj++) {
                    mma8(acc[mi][nj], al, bh[nj]);
                    mma8(acc[mi][nj], ah, bh[nj]);
                }
            }
        }
        __syncthreads();
    }
#pragma unroll
    for (int mi = 0; mi < 4; mi++)
#pragma unroll
        for (int nj = 0; nj < 4; nj++) {
            int gm = m0 + wm + mi * 16 + r;
            int gn = n0 + wn + nj * 8 + 2 * c;
            *(float2*)&C[(size_t)gm * ldc + gn]       = make_float2(acc[mi][nj].x, acc[mi][nj].y);
            *(float2*)&C[(size_t)(gm + 8) * ldc + gn] = make_float2(acc[mi][nj].z, acc[mi][nj].w);
        }
}

// Fused QKV projection (2-term): grid (18, 32)
__global__ void __launch_bounds__(256) gemm_qkv(const float* __restrict__ x,
                                                const float* __restrict__ wq,
                                                const float* __restrict__ wk,
                                                const float* __restrict__ wv,
                                                float* __restrict__ q,
                                                float* __restrict__ k,
                                                float* __restrict__ v) {
    const int nb = blockIdx.x;
    const int sel = nb / 6;
    const int n0 = (nb % 6) * 128;
    const int m0 = blockIdx.y * 128;
    const float* W = (sel == 0) ? wq : (sel == 1) ? wk : wv;
    float* O = (sel == 0) ? q : (sel == 1) ? k : v;
    gemm2_body(x, W, O, C_, C_, C_, C_, m0, n0);
}

// Final projection (2-term): grid (6, 32)
__global__ void __launch_bounds__(256) gemm_final(const float* __restrict__ A,
                                                  const float* __restrict__ Wo,
                                                  float* __restrict__ C) {
    gemm2_body(A, Wo, C, C_, C_, C_, C_, blockIdx.y * 128, blockIdx.x * 128);
}

// ---------------------------------------------------------------------------
// Scores -> store UNNORMALIZED exp(0.125*QK) (masked->0) + row partial sums.
// 2-term. grid (16, 16, 24)
// ---------------------------------------------------------------------------
__global__ void __launch_bounds__(256) scores_tc(const float* __restrict__ Q,
                                                 const float* __restrict__ Kt,
                                                 float* __restrict__ W,
                                                 float* __restrict__ partial) {
    const int z = blockIdx.z;
    const int b = z / H_, h = z % H_;
    const int m0 = blockIdx.y * 128, n0 = blockIdx.x * 128;
    const int tid = threadIdx.x;
    float* Cz = W + (size_t)z * T_ * T_;

    if (n0 > m0) {  // fully masked tile -> zeros; no partials
        const float4 zz = make_float4(0, 0, 0, 0);
        for (int idx = tid; idx < 128 * 32; idx += 256) {
            int row = idx >> 5, c4 = (idx & 31) << 2;
            *(float4*)&Cz[(size_t)(m0 + row) * T_ + n0 + c4] = zz;
        }
        return;
    }

    __shared__ float As[2][128][SKF], Bs[2][128][SKF];
    __shared__ float spart[128][4];
    const int warp = tid >> 5, lane = tid & 31;
    const int wm = (warp >> 2) * 64, wn = (warp & 3) * 32;
    const int r = lane >> 2, c = lane & 3;
    const float* Ap = Q + (size_t)b * T_ * C_ + h * DH_;
    const float* Bp = Kt + (size_t)b * T_ * C_ + h * DH_;
    const int row0 = tid >> 2, ko0 = (tid & 3) << 2;
    const int row1 = row0 + 64;

    float4 acc[4][4];
#pragma unroll
    for (int i = 0; i < 4; i++)
#pragma unroll
        for (int j = 0; j < 4; j++) acc[i][j] = make_float4(0, 0, 0, 0);

    cp16(&As[0][row0][ko0], Ap + (size_t)(m0 + row0) * C_ + ko0);
    cp16(&As[0][row1][ko0], Ap + (size_t)(m0 + row1) * C_ + ko0);
    cp16(&Bs[0][row0][ko0], Bp + (size_t)(n0 + row0) * C_ + ko0);
    cp16(&Bs[0][row1][ko0], Bp + (size_t)(n0 + row1) * C_ + ko0);
    CP_COMMIT;

#pragma unroll
    for (int it = 0; it < DH_ / 16; it++) {
        if (it + 1 < DH_ / 16) {
            int kn = (it + 1) * 16;
            int s = (it + 1) & 1;
            cp16(&As[s][row0][ko0], Ap + (size_t)(m0 + row0) * C_ + kn + ko0);
            cp16(&As[s][row1][ko0], Ap + (size_t)(m0 + row1) * C_ + kn + ko0);
            cp16(&Bs[s][row0][ko0], Bp + (size_t)(n0 + row0) * C_ + kn + ko0);
            cp16(&Bs[s][row1][ko0], Bp + (size_t)(n0 + row1) * C_ + kn + ko0);
            CP_COMMIT;
            CP_WAIT1;
        } else {
            CP_WAIT0;
        }
        __syncthreads();
        const float (*Af)[SKF] = As[it & 1];
        const float (*Bf)[SKF] = Bs[it & 1];
#pragma unroll
        for (int kb = 0; kb < 16; kb += 8) {
            uint32_t bh[4][2];
#pragma unroll
            for (int nj = 0; nj < 4; nj++) {
                int col = wn + nj * 8 + r;
                bh[nj][0] = f2tf(Bf[col][kb + c]);
                bh[nj][1] = f2tf(Bf[col][kb + c + 4]);
            }
#pragma unroll
            for (int mi = 0; mi < 4; mi++) {
                int rw = wm + mi * 16 + r;
                uint32_t ah[4], al[4];
                split_lo(Af[rw][kb + c],         ah[0], al[0]);
                split_lo(Af[rw + 8][kb + c],     ah[1], al[1]);
                split_lo(Af[rw][kb + c + 4],     ah[2], al[2]);
                split_lo(Af[rw + 8][kb + c + 4], ah[3], al[3]);
#pragma unroll
                for (int nj = 0; nj < 4; nj++) {
                    mma8(acc[mi][nj], al, bh[nj]);
                    mma8(acc[mi][nj], ah, bh[nj]);
                }
            }
        }
        __syncthreads();
    }

    const bool diag = (n0 == m0);
#pragma unroll
    for (int mi = 0; mi < 4; mi++) {
        float se0 = 0.0f, se1 = 0.0f;
        int gm = m0 + wm + mi * 16 + r;
#pragma unroll
        for (int nj = 0; nj < 4; nj++) {
            int gn = n0 + wn + nj * 8 + 2 * c;
            float e0 = exp2f(0.125f * LOG2E * acc[mi][nj].x);
            float e1 = exp2f(0.125f * LOG2E * acc[mi][nj].y);
            float e2 = exp2f(0.125f * LOG2E * acc[mi][nj].z);
            float e3 = exp2f(0.125f * LOG2E * acc[mi][nj].w);
            if (diag) {
                if (gn > gm) e0 = 0.0f;
                if (gn + 1 > gm) e1 = 0.0f;
                if (gn > gm + 8) e2 = 0.0f;
                if (gn + 1 > gm + 8) e3 = 0.0f;
            }
            se0 += e0 + e1;
            se1 += e2 + e3;
            *(float2*)&Cz[(size_t)gm * T_ + gn]       = make_float2(e0, e1);
            *(float2*)&Cz[(size_t)(gm + 8) * T_ + gn] = make_float2(e2, e3);
        }
        se0 += __shfl_xor_sync(0xffffffffu, se0, 1);
        se0 += __shfl_xor_sync(0xffffffffu, se0, 2);
        se1 += __shfl_xor_sync(0xffffffffu, se1, 1);
        se1 += __shfl_xor_sync(0xffffffffu, se1, 2);
        if (c == 0) {
            spart[wm + mi * 16 + r][warp & 3]     = se0;
            spart[wm + mi * 16 + r + 8][warp & 3] = se1;
        }
    }
    __syncthreads();
    if (tid < 128) {
        float s = spart[tid][0] + spart[tid][1] + spart[tid][2] + spart[tid][3];
        partial[((size_t)z * T_ + m0 + tid) * 16 + (n0 >> 7)] = s;
    }
}

// ---------------------------------------------------------------------------
// Normalize weights in place (computes invsum from partials inline).
// ---------------------------------------------------------------------------
__global__ void __launch_bounds__(128) normalize_kernel(float* __restrict__ W,
                                                        const float* __restrict__ partial) {
    const int rg = blockIdx.x;
    const int i = rg % T_;
    __shared__ float silv;
    if (threadIdx.x == 0) {
        const float* p = partial + (size_t)rg * 16;
        const int ntmax = i >> 7;
        float s = 0.0f;
        for (int nt = 0; nt <= ntmax; nt++) s += p[nt];
        silv = 1.0f / s;
    }
    __syncthreads();
    const float il = silv;
    const int n4 = (i + 4) >> 2;
    float4* row = (float4*)(W + (size_t)rg * T_);
    for (int j = threadIdx.x; j < n4; j += 128) {
        float4 v = row[j];
        v.x *= il; v.y *= il; v.z *= il; v.w *= il;
        row[j] = v;
    }
}

// ---------------------------------------------------------------------------
// PV k-split, 2-term. V stored k-major [16][SVF]. grid (4, 16, 24).
// ---------------------------------------------------------------------------
__global__ void __launch_bounds__(256, 4) pv_split_tc(const float* __restrict__ W,
                                                      const float* __restrict__ V,
                                                      float* __restrict__ part) {
    const int ck = blockIdx.x;
    const int mt = 15 - blockIdx.y;
    const int z = blockIdx.z;
    const int m0 = mt * 128;
    const int kbeg = ck * 512;
    const int kend = min(kbeg + 512, m0 + 128);
    if (kbeg >= kend) return;

    const int b = z / H_, h = z % H_;
    const int tid = threadIdx.x;
    const int warp = tid >> 5, lane = tid & 31;
    const int wm = (warp >> 2) * 64, wn = (warp & 3) * 16;
    const int r = lane >> 2, c = lane & 3;

    const float* Wz = W + (size_t)z * T_ * T_;
    const float* Vp = V + (size_t)b * T_ * C_ + h * DH_;

    __shared__ float As[2][128][SKF];
    __shared__ float Vs[2][16][SVF];

    const int row0 = tid >> 2, ko0 = (tid & 3) << 2;
    const int row1 = row0 + 64;
    const int kr = tid >> 4, nc = (tid & 15) << 2;

    float4 acc[4][2];
#pragma unroll
    for (int i = 0; i < 4; i++)
#pragma unroll
        for (int j = 0; j < 2; j++) acc[i][j] = make_float4(0, 0, 0, 0);

    const int niter = (kend - kbeg) / 16;
    cp16(&As[0][row0][ko0], Wz + (size_t)(m0 + row0) * T_ + kbeg + ko0);
    cp16(&As[0][row1][ko0], Wz + (size_t)(m0 + row1) * T_ + kbeg + ko0);
    cp16(&Vs[0][kr][nc],    Vp + (size_t)(kbeg + kr) * C_ + nc);
    CP_COMMIT;

    for (int it = 0; it < niter; it++) {
        if (it + 1 < niter) {
            int kn = kbeg + (it + 1) * 16;
            int s = (it + 1) & 1;
            cp16(&As[s][row0][ko0], Wz + (size_t)(m0 + row0) * T_ + kn + ko0);
            cp16(&As[s][row1][ko0], Wz + (size_t)(m0 + row1) * T_ + kn + ko0);
            cp16(&Vs[s][kr][nc],    Vp + (size_t)(kn + kr) * C_ + nc);
            CP_COMMIT;
            CP_WAIT1;
        } else {
            CP_WAIT0;
        }
        __syncthreads();
        const float (*Af)[SKF] = As[it & 1];
        const float (*Vf)[SVF] = Vs[it & 1];
#pragma unroll
        for (int kb = 0; kb < 16; kb += 8) {
            uint32_t bh[2][2];
#pragma unroll
            for (int nj = 0; nj < 2; nj++) {
                int col = wn + nj * 8 + r;
                bh[nj][0] = f2tf(Vf[kb + c][col]);
                bh[nj][1] = f2tf(Vf[kb + c + 4][col]);
            }
#pragma unroll
            for (int mi = 0; mi < 4; mi++) {
                int rw = wm + mi * 16 + r;
                uint32_t ah[4], al[4];
                split_lo(Af[rw][kb + c],         ah[0], al[0]);
                split_lo(Af[rw + 8][kb + c],     ah[1], al[1]);
                split_lo(Af[rw][kb + c + 4],     ah[2], al[2]);
                split_lo(Af[rw + 8][kb + c + 4], ah[3], al[3]);
#pragma unroll
                for (int nj = 0; nj < 2; nj++) {
                    mma8(acc[mi][nj], al, bh[nj]);
                    mma8(acc[mi][nj], ah, bh[nj]);
                }
            }
        }
        __syncthreads();
    }

    float* P = part + ((size_t)(z * 16 + mt) * 4 + ck) * (128 * DH_);
#pragma unroll
    for (int mi = 0; mi < 4; mi++)
#pragma unroll
        for (int nj = 0; nj < 2; nj++) {
            int lr = wm + mi * 16 + r;
            int gn = wn + nj * 8 + 2 * c;
            *(float2*)&P[(size_t)lr * DH_ + gn]       = make_float2(acc[mi][nj].x, acc[mi][nj].y);
            *(float2*)&P[(size_t)(lr + 8) * DH_ + gn] = make_float2(acc[mi][nj].z, acc[mi][nj].w);
        }
}

// ---------------------------------------------------------------------------
// Sum pv partials -> O (g_att layout [B,T,C]). grid (384), 256 thr.
// ---------------------------------------------------------------------------
__global__ void __launch_bounds__(256) pv_reduce(const float* __restrict__ part,
                                                 float* __restrict__ O) {
    const int blk = blockIdx.x;            // z*16 + mt
    const int z = blk >> 4, mt = blk & 15;
    const int b = z / H_, h = z % H_;
    const int m0 = mt * 128;
    const int nch = (mt >> 2) + 1;
    const float* p = part + (size_t)blk * 4 * (128 * DH_);

    for (int idx = threadIdx.x * 4; idx < 128 * DH_; idx += 256 * 4) {
        float4 s = *(const float4*)(p + idx);
        for (int c2 = 1; c2 < nch; c2++) {
            float4 t = *(const float4*)(p + (size_t)c2 * 128 * DH_ + idx);
            s.x += t.x; s.y += t.y; s.z += t.z; s.w += t.w;
        }
        const int row = idx >> 6, n = idx & 63;
        *(float4*)&O[(size_t)(b * T_ + m0 + row) * C_ + h * DH_ + n] = s;
    }
}

// ---------------------------------------------------------------------------
extern "C" void kernel_launch(void* const* d_in, const int* in_sizes, int n_in,
                              void* d_out, int out_size) {
    const float* x   = (const float*)d_in[0];
    const float* w_q = (const float*)d_in[1];
    const float* w_k = (const float*)d_in[2];
    const float* w_v = (const float*)d_in[3];
    const float* w_o = (const float*)d_in[4];

    float* qp; cudaGetSymbolAddress((void**)&qp, g_q);
    float* kp; cudaGetSymbolAddress((void**)&kp, g_k);
    float* vp; cudaGetSymbolAddress((void**)&vp, g_v);
    float* ap; cudaGetSymbolAddress((void**)&ap, g_att);
    float* pp; cudaGetSymbolAddress((void**)&pp, g_partial);
    float* vv; cudaGetSymbolAddress((void**)&vv, g_pvpart);

    float* final_out = (float*)d_out;                       // [B,T,C]
    float* w_out = (float*)d_out + (size_t)B_ * T_ * C_;    // [B,H,T,T]

    const dim3 blk(256);

    gemm_qkv<<<dim3(18, 32), blk>>>(x, w_q, w_k, w_v, qp, kp, vp);

    scores_tc<<<dim3(T_ / 128, T_ / 128, B_ * H_), blk>>>(qp, kp, w_out, pp);

    normalize_kernel<<<B_ * H_ * T_, 128>>>(w_out, pp);

    pv_split_tc<<<dim3(4, 16, 24), blk>>>(w_out, vp, vv);

    pv_reduce<<<B_ * H_ * 16, blk>>>(vv, ap);

    gemm_final<<<dim3(6, 32), blk>>>(ap, w_o, final_out);
}